// round 3
// baseline (speedup 1.0000x reference)
#include <cuda_runtime.h>
#include <cuda_bf16.h>
#include <math.h>
#include <cstdint>

// Problem constants
#define T_ 4096
#define B_ 4
#define E_ 512
#define CK_ 1024
#define H_ 8
#define HD_ 64
#define NB_ (B_ * E_)   // 2048

// ---------------- scratch (__device__ globals; no allocs allowed) ----------
__device__ float g_q  [(size_t)T_ * B_ * E_];
__device__ float g_kin[(size_t)CK_ * B_ * E_];
__device__ float g_vin[(size_t)CK_ * B_ * E_];
__device__ float g_k  [(size_t)CK_ * B_ * E_];
__device__ float g_v  [(size_t)CK_ * B_ * E_];
__device__ float g_att[(size_t)T_ * B_ * E_];
__device__ __nv_bfloat16 g_xth[(size_t)NB_ * T_];  // X^T hi  [2048][4096]
__device__ __nv_bfloat16 g_xtl[(size_t)NB_ * T_];  // X^T lo

// ---------------- helpers ---------------------------------------------------
__device__ __forceinline__ uint32_t smem_u32(const void* p) {
    uint32_t a;
    asm("{ .reg .u64 t; cvta.to.shared.u64 t, %1; cvt.u32.u64 %0, t; }" : "=r"(a) : "l"(p));
    return a;
}
__device__ __forceinline__ uint32_t swz(uint32_t off) { return off ^ ((off >> 3) & 0x70); }

#define LDSM_X4(r0, r1, r2, r3, addr) \
    asm volatile("ldmatrix.sync.aligned.m8n8.x4.shared.b16 {%0,%1,%2,%3}, [%4];" \
        : "=r"(r0), "=r"(r1), "=r"(r2), "=r"(r3) : "r"(addr))

__device__ __forceinline__ void mma16816(float* c, const uint32_t* a, const uint32_t* b) {
    asm volatile("mma.sync.aligned.m16n8k16.row.col.f32.bf16.bf16.f32 "
                 "{%0,%1,%2,%3}, {%4,%5,%6,%7}, {%8,%9}, {%0,%1,%2,%3};"
                 : "+f"(c[0]), "+f"(c[1]), "+f"(c[2]), "+f"(c[3])
                 : "r"(a[0]), "r"(a[1]), "r"(a[2]), "r"(a[3]), "r"(b[0]), "r"(b[1]));
}

// pack fp32 pair -> (hi bf16x2, lo bf16x2)
__device__ __forceinline__ void split2(float x0, float x1, uint32_t& hp, uint32_t& lp) {
    __nv_bfloat16 h0 = __float2bfloat16(x0);
    __nv_bfloat16 h1 = __float2bfloat16(x1);
    __nv_bfloat16 l0 = __float2bfloat16(x0 - __bfloat162float(h0));
    __nv_bfloat16 l1 = __float2bfloat16(x1 - __bfloat162float(h1));
    hp = (uint32_t)__bfloat16_as_ushort(h0) | ((uint32_t)__bfloat16_as_ushort(h1) << 16);
    lp = (uint32_t)__bfloat16_as_ushort(l0) | ((uint32_t)__bfloat16_as_ushort(l1) << 16);
}

// ---------------------------------------------------------------------------
// Transpose + bf16 split: X[T][2048] fp32 -> Xt hi/lo [2048][T] bf16
// ---------------------------------------------------------------------------
__global__ __launch_bounds__(256) void transpose_split_kernel(
    const float* __restrict__ X, __nv_bfloat16* __restrict__ Xh, __nv_bfloat16* __restrict__ Xl)
{
    __shared__ float tile[32][33];
    int n0 = blockIdx.x * 32, t0 = blockIdx.y * 32;
    int tx = threadIdx.x & 31, ty = threadIdx.x >> 5;
#pragma unroll
    for (int i = 0; i < 4; i++) {
        int r = ty + i * 8;
        tile[r][tx] = X[(size_t)(t0 + r) * NB_ + n0 + tx];
    }
    __syncthreads();
#pragma unroll
    for (int i = 0; i < 4; i++) {
        int r = ty + i * 8;
        float x = tile[tx][r];
        __nv_bfloat16 h = __float2bfloat16(x);
        __nv_bfloat16 l = __float2bfloat16(x - __bfloat162float(h));
        size_t o = (size_t)(n0 + r) * T_ + t0 + tx;
        Xh[o] = h; Xl[o] = l;
    }
}

// ---------------------------------------------------------------------------
// HMMA split-bf16 GEMM: C[M,N] = (A[M,K] · B[N,K]^T + bias) * scale
//   3 passes: Ah·Bh + Ah·Bl + Al·Bh into shared fp32 accumulators.
// Tile 128x128, K-chunk 64, 256 threads (8 warps, 4x2), single-buffered smem.
// ---------------------------------------------------------------------------
template<bool B_PRESPLIT, bool HAS_BIAS>
__global__ __launch_bounds__(256, 2) void hmma_gemm(
    const float* __restrict__ A,
    const float* __restrict__ Bf,
    const __nv_bfloat16* __restrict__ Bh_g, const __nv_bfloat16* __restrict__ Bl_g,
    const float* __restrict__ bias, float* __restrict__ C,
    int M, int N, int K, float scale)
{
    extern __shared__ char sm[];
    constexpr uint32_t SM_AH = 0, SM_AL = 16384, SM_BH = 32768, SM_BL = 49152;

    const int tid = threadIdx.x, wid = tid >> 5, lane = tid & 31;
    const int warp_m = wid & 3;          // 4 warps along M (32 rows each)
    const int warp_n = wid >> 2;         // 2 warps along N (64 cols each)
    const int m0 = blockIdx.y * 128, n0 = blockIdx.x * 128;
    const uint32_t sb = smem_u32(sm);

    // ldmatrix per-lane address components
    const int a_row = warp_m * 32 + (lane & 15);
    const int a_k   = (lane >> 4) * 8;
    const int b_n   = warp_n * 64 + (lane & 7) + (lane >> 4) * 8;
    const int b_k   = ((lane >> 3) & 1) * 8;

    float acc[2][8][4];
#pragma unroll
    for (int i = 0; i < 2; i++)
#pragma unroll
        for (int j = 0; j < 8; j++)
#pragma unroll
            for (int r = 0; r < 4; r++) acc[i][j][r] = 0.f;

    const int nchunks = K >> 6;
    for (int kt = 0; kt < nchunks; kt++) {
        const int k0 = kt << 6;
        // ---- stage A (fp32 -> hi/lo bf16), 128 rows x 64 k
#pragma unroll
        for (int l = 0; l < 8; l++) {
            int idx = l * 256 + tid;
            int row = idx >> 4, c4 = (idx & 15) << 2;
            float4 a = *(const float4*)(A + (size_t)(m0 + row) * K + k0 + c4);
            uint32_t off = swz((uint32_t)row * 128u + (uint32_t)c4 * 2u);
            uint32_t h0, l0, h1, l1;
            split2(a.x, a.y, h0, l0);
            split2(a.z, a.w, h1, l1);
            *(uint2*)(sm + SM_AH + off) = make_uint2(h0, h1);
            *(uint2*)(sm + SM_AL + off) = make_uint2(l0, l1);
        }
        // ---- stage B
        if (B_PRESPLIT) {
#pragma unroll
            for (int l = 0; l < 4; l++) {
                int idx = l * 256 + tid;
                int row = idx >> 3, c16 = (idx & 7) << 4;   // byte col
                uint32_t off = swz((uint32_t)row * 128u + (uint32_t)c16);
                size_t g = ((size_t)(n0 + row) * K + k0) * 2 + c16;
                *(uint4*)(sm + SM_BH + off) = *(const uint4*)((const char*)Bh_g + g);
                *(uint4*)(sm + SM_BL + off) = *(const uint4*)((const char*)Bl_g + g);
            }
        } else {
#pragma unroll
            for (int l = 0; l < 8; l++) {
                int idx = l * 256 + tid;
                int row = idx >> 4, c4 = (idx & 15) << 2;
                float4 b = *(const float4*)(Bf + (size_t)(n0 + row) * K + k0 + c4);
                uint32_t off = swz((uint32_t)row * 128u + (uint32_t)c4 * 2u);
                uint32_t h0, l0, h1, l1;
                split2(b.x, b.y, h0, l0);
                split2(b.z, b.w, h1, l1);
                *(uint2*)(sm + SM_BH + off) = make_uint2(h0, h1);
                *(uint2*)(sm + SM_BL + off) = make_uint2(l0, l1);
            }
        }
        __syncthreads();

        // ---- 3 split passes over this K-chunk
#pragma unroll
        for (int pass = 0; pass < 3; pass++) {
            const uint32_t ab = sb + (pass == 2 ? SM_AL : SM_AH);
            const uint32_t bb = sb + (pass == 1 ? SM_BL : SM_BH);
#pragma unroll
            for (int ks = 0; ks < 4; ks++) {
                uint32_t af[2][4], bfr[4][4];
#pragma unroll
                for (int mt = 0; mt < 2; mt++) {
                    uint32_t ad = ab + swz((uint32_t)(a_row + mt * 16) * 128u
                                           + (uint32_t)(ks * 16 + a_k) * 2u);
                    LDSM_X4(af[mt][0], af[mt][1], af[mt][2], af[mt][3], ad);
                }
#pragma unroll
                for (int nt = 0; nt < 4; nt++) {
                    uint32_t bd = bb + swz((uint32_t)(b_n + nt * 16) * 128u
                                           + (uint32_t)(ks * 16 + b_k) * 2u);
                    LDSM_X4(bfr[nt][0], bfr[nt][1], bfr[nt][2], bfr[nt][3], bd);
                }
#pragma unroll
                for (int mt = 0; mt < 2; mt++)
#pragma unroll
                    for (int n8 = 0; n8 < 8; n8++)
                        mma16816(acc[mt][n8], af[mt], &bfr[n8 >> 1][(n8 & 1) * 2]);
            }
        }
        __syncthreads();
    }

    // ---- epilogue
    const int g = lane >> 2, t = lane & 3;
#pragma unroll
    for (int mt = 0; mt < 2; mt++) {
        int r0 = m0 + warp_m * 32 + mt * 16 + g;
#pragma unroll
        for (int n8 = 0; n8 < 8; n8++) {
            int col = n0 + warp_n * 64 + n8 * 8 + t * 2;
            float b0 = 0.f, b1 = 0.f;
            if (HAS_BIAS) { b0 = bias[col]; b1 = bias[col + 1]; }
            float2 v0 = make_float2((acc[mt][n8][0] + b0) * scale,
                                    (acc[mt][n8][1] + b1) * scale);
            float2 v1 = make_float2((acc[mt][n8][2] + b0) * scale,
                                    (acc[mt][n8][3] + b1) * scale);
            *(float2*)(C + (size_t)r0 * N + col) = v0;
            *(float2*)(C + (size_t)(r0 + 8) * N + col) = v1;
        }
    }
}

// ---------------------------------------------------------------------------
// Flash attention (fp32, unchanged from round 1 — known correct)
// ---------------------------------------------------------------------------
__device__ __forceinline__ float redmax16(float v) {
    v = fmaxf(v, __shfl_xor_sync(0xffffffffu, v, 1));
    v = fmaxf(v, __shfl_xor_sync(0xffffffffu, v, 2));
    v = fmaxf(v, __shfl_xor_sync(0xffffffffu, v, 4));
    v = fmaxf(v, __shfl_xor_sync(0xffffffffu, v, 8));
    return v;
}
__device__ __forceinline__ float redsum16(float v) {
    v += __shfl_xor_sync(0xffffffffu, v, 1);
    v += __shfl_xor_sync(0xffffffffu, v, 2);
    v += __shfl_xor_sync(0xffffffffu, v, 4);
    v += __shfl_xor_sync(0xffffffffu, v, 8);
    return v;
}

__global__ __launch_bounds__(256) void flash_kernel(
    const float* __restrict__ Q, const float* __restrict__ Kb,
    const float* __restrict__ Vb, float* __restrict__ O)
{
    extern __shared__ float smf[];
    constexpr int PAD = 68;
    float* Qs = smf;
    float* Ks = smf + 64 * PAD;
    float* Vs = smf + 2 * 64 * PAD;

    const int tid = threadIdx.x;
    const int tx = tid & 15;
    const int ty = tid >> 4;
    const int bh = blockIdx.y;
    const int b  = bh >> 3;
    const int h  = bh & 7;
    const int t0 = blockIdx.x * 64;

#pragma unroll
    for (int l = 0; l < 4; l++) {
        int idx = tid + l * 256;
        int r  = idx >> 4;
        int c4 = (idx & 15) << 2;
        *(float4*)&Qs[r * PAD + c4] =
            *(const float4*)(Q + ((size_t)(t0 + r) * B_ + b) * E_ + h * 64 + c4);
    }

    float m_run[4], l_run[4], o_acc[4][4];
#pragma unroll
    for (int i = 0; i < 4; i++) {
        m_run[i] = -1e30f; l_run[i] = 0.f;
#pragma unroll
        for (int j = 0; j < 4; j++) o_acc[i][j] = 0.f;
    }
    __syncthreads();

    for (int kt = 0; kt < CK_ / 64; kt++) {
#pragma unroll
        for (int l = 0; l < 4; l++) {
            int idx = tid + l * 256;
            int r  = idx >> 4;
            int c4 = (idx & 15) << 2;
            size_t gg = ((size_t)(kt * 64 + r) * B_ + b) * E_ + h * 64 + c4;
            *(float4*)&Ks[r * PAD + c4] = *(const float4*)(Kb + gg);
            *(float4*)&Vs[r * PAD + c4] = *(const float4*)(Vb + gg);
        }
        __syncthreads();

        float s[4][4];
#pragma unroll
        for (int i = 0; i < 4; i++)
#pragma unroll
            for (int j = 0; j < 4; j++) s[i][j] = 0.f;

#pragma unroll
        for (int d = 0; d < 64; d += 4) {
            float4 q4[4], k4[4];
#pragma unroll
            for (int i = 0; i < 4; i++)
                q4[i] = *(const float4*)&Qs[(ty + 16 * i) * PAD + d];
#pragma unroll
            for (int j = 0; j < 4; j++)
                k4[j] = *(const float4*)&Ks[(tx + 16 * j) * PAD + d];
#pragma unroll
            for (int i = 0; i < 4; i++)
#pragma unroll
                for (int j = 0; j < 4; j++) {
                    s[i][j] = fmaf(q4[i].x, k4[j].x, s[i][j]);
                    s[i][j] = fmaf(q4[i].y, k4[j].y, s[i][j]);
                    s[i][j] = fmaf(q4[i].z, k4[j].z, s[i][j]);
                    s[i][j] = fmaf(q4[i].w, k4[j].w, s[i][j]);
                }
        }

        float p[4][4];
#pragma unroll
        for (int i = 0; i < 4; i++) {
            float mn = fmaxf(fmaxf(s[i][0], s[i][1]), fmaxf(s[i][2], s[i][3]));
            mn = redmax16(mn);
            mn = fmaxf(mn, m_run[i]);
            float rs = 0.f;
#pragma unroll
            for (int j = 0; j < 4; j++) {
                p[i][j] = __expf(s[i][j] - mn);
                rs += p[i][j];
            }
            rs = redsum16(rs);
            float f = __expf(m_run[i] - mn);
            l_run[i] = l_run[i] * f + rs;
            m_run[i] = mn;
#pragma unroll
            for (int j = 0; j < 4; j++) o_acc[i][j] *= f;
        }
        __syncthreads();

#pragma unroll
        for (int i = 0; i < 4; i++)
#pragma unroll
            for (int j = 0; j < 4; j++)
                Ks[(ty + 16 * i) * PAD + tx + 16 * j] = p[i][j];
        __syncthreads();

#pragma unroll
        for (int k = 0; k < 64; k += 4) {
            float4 v4[4], p4[4];
#pragma unroll
            for (int kk = 0; kk < 4; kk++)
                v4[kk] = *(const float4*)&Vs[(k + kk) * PAD + tx * 4];
#pragma unroll
            for (int i = 0; i < 4; i++)
                p4[i] = *(const float4*)&Ks[(ty + 16 * i) * PAD + k];
#pragma unroll
            for (int i = 0; i < 4; i++) {
                o_acc[i][0] = fmaf(p4[i].x, v4[0].x, o_acc[i][0]);
                o_acc[i][1] = fmaf(p4[i].x, v4[0].y, o_acc[i][1]);
                o_acc[i][2] = fmaf(p4[i].x, v4[0].z, o_acc[i][2]);
                o_acc[i][3] = fmaf(p4[i].x, v4[0].w, o_acc[i][3]);
                o_acc[i][0] = fmaf(p4[i].y, v4[1].x, o_acc[i][0]);
                o_acc[i][1] = fmaf(p4[i].y, v4[1].y, o_acc[i][1]);
                o_acc[i][2] = fmaf(p4[i].y, v4[1].z, o_acc[i][2]);
                o_acc[i][3] = fmaf(p4[i].y, v4[1].w, o_acc[i][3]);
                o_acc[i][0] = fmaf(p4[i].z, v4[2].x, o_acc[i][0]);
                o_acc[i][1] = fmaf(p4[i].z, v4[2].y, o_acc[i][1]);
                o_acc[i][2] = fmaf(p4[i].z, v4[2].z, o_acc[i][2]);
                o_acc[i][3] = fmaf(p4[i].z, v4[2].w, o_acc[i][3]);
                o_acc[i][0] = fmaf(p4[i].w, v4[3].x, o_acc[i][0]);
                o_acc[i][1] = fmaf(p4[i].w, v4[3].y, o_acc[i][1]);
                o_acc[i][2] = fmaf(p4[i].w, v4[3].z, o_acc[i][2]);
                o_acc[i][3] = fmaf(p4[i].w, v4[3].w, o_acc[i][3]);
            }
        }
        __syncthreads();
    }

#pragma unroll
    for (int i = 0; i < 4; i++) {
        float inv = 1.f / l_run[i];
        int r = ty + 16 * i;
        float4 w = make_float4(o_acc[i][0] * inv, o_acc[i][1] * inv,
                               o_acc[i][2] * inv, o_acc[i][3] * inv);
        *(float4*)(O + ((size_t)(t0 + r) * B_ + b) * E_ + h * 64 + tx * 4) = w;
    }
}

// ---------------------------------------------------------------------------
extern "C" void kernel_launch(void* const* d_in, const int* in_sizes, int n_in,
                              void* d_out, int out_size)
{
    const float* query = (const float*)d_in[0];
    const float* Wq    = (const float*)d_in[1];
    const float* bq    = (const float*)d_in[2];
    const float* Wk    = (const float*)d_in[3];
    const float* bk    = (const float*)d_in[4];
    const float* Wv    = (const float*)d_in[5];
    const float* bv    = (const float*)d_in[6];
    const float* Wck   = (const float*)d_in[7];
    const float* Wcv   = (const float*)d_in[8];
    const float* Wo    = (const float*)d_in[9];
    const float* bo    = (const float*)d_in[10];
    float* out = (float*)d_out;

    float *q, *kin, *vin, *k, *v, *att;
    __nv_bfloat16 *xth, *xtl;
    cudaGetSymbolAddress((void**)&q,   g_q);
    cudaGetSymbolAddress((void**)&kin, g_kin);
    cudaGetSymbolAddress((void**)&vin, g_vin);
    cudaGetSymbolAddress((void**)&k,   g_k);
    cudaGetSymbolAddress((void**)&v,   g_v);
    cudaGetSymbolAddress((void**)&att, g_att);
    cudaGetSymbolAddress((void**)&xth, g_xth);
    cudaGetSymbolAddress((void**)&xtl, g_xtl);

    const int GSM = 65536;
    cudaFuncSetAttribute(hmma_gemm<false, true>,
                         cudaFuncAttributeMaxDynamicSharedMemorySize, GSM);
    cudaFuncSetAttribute(hmma_gemm<true, false>,
                         cudaFuncAttributeMaxDynamicSharedMemorySize, GSM);

    const float qscale = 0.125f;  // 64^-0.5

    // 0) Transpose + split X -> Xt hi/lo  [2048][4096]
    transpose_split_kernel<<<dim3(NB_ / 32, T_ / 32), 256>>>(query, xth, xtl);

    // 1) q = (X @ Wq^T + bq) * scale        [16384 x 512 x 512]
    hmma_gemm<false, true><<<dim3(E_ / 128, (T_ * B_) / 128), 256, GSM>>>(
        query, Wq, nullptr, nullptr, bq, q, T_ * B_, E_, E_, qscale);

    // 2) k_in = Wck @ X  ==  Wck[CK,T] · (Xt[2048,T])^T   [1024 x 2048 x 4096]
    hmma_gemm<true, false><<<dim3(NB_ / 128, CK_ / 128), 256, GSM>>>(
        Wck, nullptr, xth, xtl, nullptr, kin, CK_, NB_, T_, 1.f);

    // 3) v_in = Wcv @ X
    hmma_gemm<true, false><<<dim3(NB_ / 128, CK_ / 128), 256, GSM>>>(
        Wcv, nullptr, xth, xtl, nullptr, vin, CK_, NB_, T_, 1.f);

    // 4) k = k_in @ Wk^T + bk               [4096 x 512 x 512]
    hmma_gemm<false, true><<<dim3(E_ / 128, (CK_ * B_) / 128), 256, GSM>>>(
        kin, Wk, nullptr, nullptr, bk, k, CK_ * B_, E_, E_, 1.f);

    // 5) v = v_in @ Wv^T + bv
    hmma_gemm<false, true><<<dim3(E_ / 128, (CK_ * B_) / 128), 256, GSM>>>(
        vin, Wv, nullptr, nullptr, bv, v, CK_ * B_, E_, E_, 1.f);

    // 6) attention (fp32 flash)
    const int FSM = 3 * 64 * 68 * (int)sizeof(float);
    cudaFuncSetAttribute(flash_kernel,
                         cudaFuncAttributeMaxDynamicSharedMemorySize, FSM);
    flash_kernel<<<dim3(T_ / 64, B_ * H_), 256, FSM>>>(q, k, v, att);

    // 7) out = att @ Wo^T + bo              [16384 x 512 x 512]
    hmma_gemm<false, true><<<dim3(E_ / 128, (T_ * B_) / 128), 256, GSM>>>(
        att, Wo, nullptr, nullptr, bo, out, T_ * B_, E_, E_, 1.f);

    (void)in_sizes; (void)n_in; (void)out_size;
}

// round 4
// speedup vs baseline: 2.2919x; 2.2919x over previous
#include <cuda_runtime.h>
#include <cuda_bf16.h>
#include <math.h>
#include <cstdint>

// Problem constants
#define T_ 4096
#define B_ 4
#define E_ 512
#define CK_ 1024
#define H_ 8
#define HD_ 64
#define NB_ (B_ * E_)   // 2048

typedef __nv_bfloat16 bf16;

// ---------------- scratch (__device__ globals) ------------------------------
__device__ float g_part[(size_t)4 * CK_ * NB_];          // split-K partials (32MB)
__device__ bf16 g_xnth[(size_t)T_ * NB_],  g_xntl[(size_t)T_ * NB_];   // X   [16384][512]
__device__ bf16 g_xth [(size_t)NB_ * T_],  g_xtl [(size_t)NB_ * T_];   // X^T [2048][4096]
__device__ bf16 g_wqh[E_*E_], g_wql[E_*E_], g_wkh[E_*E_], g_wkl[E_*E_];
__device__ bf16 g_wvh[E_*E_], g_wvl[E_*E_], g_woh[E_*E_], g_wol[E_*E_];
__device__ bf16 g_wckh[(size_t)CK_*T_], g_wckl[(size_t)CK_*T_];
__device__ bf16 g_wcvh[(size_t)CK_*T_], g_wcvl[(size_t)CK_*T_];
__device__ bf16 g_qh [(size_t)T_*B_*E_],  g_ql [(size_t)T_*B_*E_];
__device__ bf16 g_kinh[(size_t)CK_*NB_],  g_kinl[(size_t)CK_*NB_];
__device__ bf16 g_vinh[(size_t)CK_*NB_],  g_vinl[(size_t)CK_*NB_];
__device__ bf16 g_kh [(size_t)CK_*B_*E_], g_kl [(size_t)CK_*B_*E_];
__device__ bf16 g_vh [(size_t)CK_*B_*E_], g_vl [(size_t)CK_*B_*E_];
__device__ bf16 g_atth[(size_t)T_*B_*E_], g_attl[(size_t)T_*B_*E_];

// ---------------- helpers ---------------------------------------------------
__device__ __forceinline__ uint32_t smem_u32(const void* p) {
    uint32_t a;
    asm("{ .reg .u64 t; cvta.to.shared.u64 t, %1; cvt.u32.u64 %0, t; }" : "=r"(a) : "l"(p));
    return a;
}
__device__ __forceinline__ uint32_t swz(uint32_t off) { return off ^ ((off >> 3) & 0x70); }

#define LDSM_X4(r0, r1, r2, r3, addr) \
    asm volatile("ldmatrix.sync.aligned.m8n8.x4.shared.b16 {%0,%1,%2,%3}, [%4];" \
        : "=r"(r0), "=r"(r1), "=r"(r2), "=r"(r3) : "r"(addr))
#define LDSM_X2_T(r0, r1, addr) \
    asm volatile("ldmatrix.sync.aligned.m8n8.x2.trans.shared.b16 {%0,%1}, [%2];" \
        : "=r"(r0), "=r"(r1) : "r"(addr))

__device__ __forceinline__ void mma16816(float* c, const uint32_t* a, const uint32_t* b) {
    asm volatile("mma.sync.aligned.m16n8k16.row.col.f32.bf16.bf16.f32 "
                 "{%0,%1,%2,%3}, {%4,%5,%6,%7}, {%8,%9}, {%0,%1,%2,%3};"
                 : "+f"(c[0]), "+f"(c[1]), "+f"(c[2]), "+f"(c[3])
                 : "r"(a[0]), "r"(a[1]), "r"(a[2]), "r"(a[3]), "r"(b[0]), "r"(b[1]));
}

__device__ __forceinline__ uint32_t pack_hi(float x0, float x1, uint32_t& lo) {
    bf16 h0 = __float2bfloat16(x0), h1 = __float2bfloat16(x1);
    bf16 l0 = __float2bfloat16(x0 - __bfloat162float(h0));
    bf16 l1 = __float2bfloat16(x1 - __bfloat162float(h1));
    lo = (uint32_t)__bfloat16_as_ushort(l0) | ((uint32_t)__bfloat16_as_ushort(l1) << 16);
    return (uint32_t)__bfloat16_as_ushort(h0) | ((uint32_t)__bfloat16_as_ushort(h1) << 16);
}

// ---------------------------------------------------------------------------
// Elementwise split: fp32 -> bf16 hi/lo
// ---------------------------------------------------------------------------
__global__ void split_kernel(const float* __restrict__ src,
                             bf16* __restrict__ h, bf16* __restrict__ l, int n)
{
    int i = blockIdx.x * blockDim.x + threadIdx.x;
    if (i < n) {
        float x = src[i];
        bf16 hh = __float2bfloat16(x);
        h[i] = hh;
        l[i] = __float2bfloat16(x - __bfloat162float(hh));
    }
}

// Transpose + split: X[T][2048] fp32 -> Xt hi/lo [2048][T]
__global__ __launch_bounds__(256) void transpose_split_kernel(
    const float* __restrict__ X, bf16* __restrict__ Xh, bf16* __restrict__ Xl)
{
    __shared__ float tile[32][33];
    int n0 = blockIdx.x * 32, t0 = blockIdx.y * 32;
    int tx = threadIdx.x & 31, ty = threadIdx.x >> 5;
#pragma unroll
    for (int i = 0; i < 4; i++) {
        int r = ty + i * 8;
        tile[r][tx] = X[(size_t)(t0 + r) * NB_ + n0 + tx];
    }
    __syncthreads();
#pragma unroll
    for (int i = 0; i < 4; i++) {
        int r = ty + i * 8;
        float x = tile[tx][r];
        bf16 h = __float2bfloat16(x);
        size_t o = (size_t)(n0 + r) * T_ + t0 + tx;
        Xh[o] = h; Xl[o] = __float2bfloat16(x - __bfloat162float(h));
    }
}

// split-K reduce: sum S partials (+bias) -> bf16 hi/lo
__global__ void reduce_split_kernel(const float* __restrict__ part, int S,
                                    const float* __restrict__ bias,
                                    bf16* __restrict__ Ch, bf16* __restrict__ Cl,
                                    int total, int N)
{
    int i = blockIdx.x * blockDim.x + threadIdx.x;
    if (i >= total) return;
    float s = 0.f;
    for (int z = 0; z < S; z++) s += part[(size_t)z * total + i];
    if (bias) s += bias[i % N];
    bf16 h = __float2bfloat16(s);
    Ch[i] = h;
    Cl[i] = __float2bfloat16(s - __bfloat162float(h));
}

// ---------------------------------------------------------------------------
// HMMA GEMM, all operands pre-split bf16 hi/lo, K-major [rows][K].
// C = A · B^T; 3-pass split; tile 128x128, K-chunk 64, 256 threads, 2 CTA/SM.
// MODE 0: fp32 out + bias + scale
// MODE 1: bf16 hi/lo out + bias + scale
// MODE 2: fp32 split-K partial (blockIdx.z slice of K, out offset z*M*N)
// ---------------------------------------------------------------------------
template<int MODE>
__global__ __launch_bounds__(256, 2) void hmma_ps(
    const bf16* __restrict__ Ah_g, const bf16* __restrict__ Al_g,
    const bf16* __restrict__ Bh_g, const bf16* __restrict__ Bl_g,
    const float* __restrict__ bias, float* __restrict__ Cf,
    bf16* __restrict__ Ch, bf16* __restrict__ Cl,
    int M, int N, int K, int kps, float scale)
{
    extern __shared__ char sm[];
    constexpr uint32_t SM_AH = 0, SM_AL = 16384, SM_BH = 32768, SM_BL = 49152;
    const int tid = threadIdx.x, wid = tid >> 5, lane = tid & 31;
    const int warp_m = wid & 3, warp_n = wid >> 2;
    const int m0 = blockIdx.y * 128, n0 = blockIdx.x * 128;
    const int kz = blockIdx.z * kps;
    const uint32_t sb = smem_u32(sm);

    const int a_row = warp_m * 32 + (lane & 15);
    const int a_k   = (lane >> 4) * 8;
    const int b_n   = warp_n * 64 + (lane & 7) + (lane >> 4) * 8;
    const int b_k   = ((lane >> 3) & 1) * 8;

    float acc[2][8][4];
#pragma unroll
    for (int i = 0; i < 2; i++)
#pragma unroll
        for (int j = 0; j < 8; j++)
#pragma unroll
            for (int r = 0; r < 4; r++) acc[i][j][r] = 0.f;

    const int st_row = tid >> 3, st_c16 = (tid & 7) << 4;   // per-thread base
    for (int k0 = kz; k0 < kz + kps; k0 += 64) {
        // ---- stage 4 tensors, 16KB each, pure uint4 copies
#pragma unroll
        for (int l = 0; l < 4; l++) {
            int row = st_row + l * 32;
            uint32_t off = swz((uint32_t)row * 128u + (uint32_t)st_c16);
            size_t ga = ((size_t)(m0 + row) * K + k0) * 2 + st_c16;
            size_t gb = ((size_t)(n0 + row) * K + k0) * 2 + st_c16;
            *(uint4*)(sm + SM_AH + off) = *(const uint4*)((const char*)Ah_g + ga);
            *(uint4*)(sm + SM_AL + off) = *(const uint4*)((const char*)Al_g + ga);
            *(uint4*)(sm + SM_BH + off) = *(const uint4*)((const char*)Bh_g + gb);
            *(uint4*)(sm + SM_BL + off) = *(const uint4*)((const char*)Bl_g + gb);
        }
        __syncthreads();

#pragma unroll
        for (int pass = 0; pass < 3; pass++) {
            const uint32_t ab = sb + (pass == 2 ? SM_AL : SM_AH);
            const uint32_t bb = sb + (pass == 1 ? SM_BL : SM_BH);
#pragma unroll
            for (int ks = 0; ks < 4; ks++) {
                uint32_t af[2][4], bfr[4][4];
#pragma unroll
                for (int mt = 0; mt < 2; mt++) {
                    uint32_t ad = ab + swz((uint32_t)(a_row + mt * 16) * 128u
                                           + (uint32_t)(ks * 16 + a_k) * 2u);
                    LDSM_X4(af[mt][0], af[mt][1], af[mt][2], af[mt][3], ad);
                }
#pragma unroll
                for (int nt = 0; nt < 4; nt++) {
                    uint32_t bd = bb + swz((uint32_t)(b_n + nt * 16) * 128u
                                           + (uint32_t)(ks * 16 + b_k) * 2u);
                    LDSM_X4(bfr[nt][0], bfr[nt][1], bfr[nt][2], bfr[nt][3], bd);
                }
#pragma unroll
                for (int mt = 0; mt < 2; mt++)
#pragma unroll
                    for (int n8 = 0; n8 < 8; n8++)
                        mma16816(acc[mt][n8], af[mt], &bfr[n8 >> 1][(n8 & 1) * 2]);
            }
        }
        __syncthreads();
    }

    // ---- epilogue
    const int g = lane >> 2, t = lane & 3;
#pragma unroll
    for (int mt = 0; mt < 2; mt++) {
        int r0 = m0 + warp_m * 32 + mt * 16 + g;
#pragma unroll
        for (int n8 = 0; n8 < 8; n8++) {
            int col = n0 + warp_n * 64 + n8 * 8 + t * 2;
            if (MODE == 2) {
                size_t base = (size_t)blockIdx.z * M * N;
                *(float2*)(Cf + base + (size_t)r0 * N + col) =
                    make_float2(acc[mt][n8][0], acc[mt][n8][1]);
                *(float2*)(Cf + base + (size_t)(r0 + 8) * N + col) =
                    make_float2(acc[mt][n8][2], acc[mt][n8][3]);
            } else {
                float b0 = bias ? bias[col] : 0.f, b1 = bias ? bias[col + 1] : 0.f;
                float v0 = (acc[mt][n8][0] + b0) * scale, v1 = (acc[mt][n8][1] + b1) * scale;
                float v2 = (acc[mt][n8][2] + b0) * scale, v3 = (acc[mt][n8][3] + b1) * scale;
                if (MODE == 0) {
                    *(float2*)(Cf + (size_t)r0 * N + col) = make_float2(v0, v1);
                    *(float2*)(Cf + (size_t)(r0 + 8) * N + col) = make_float2(v2, v3);
                } else {
                    uint32_t lo0, lo1;
                    uint32_t hi0 = pack_hi(v0, v1, lo0);
                    uint32_t hi1 = pack_hi(v2, v3, lo1);
                    *(uint32_t*)((char*)Ch + ((size_t)r0 * N + col) * 2) = hi0;
                    *(uint32_t*)((char*)Cl + ((size_t)r0 * N + col) * 2) = lo0;
                    *(uint32_t*)((char*)Ch + ((size_t)(r0 + 8) * N + col) * 2) = hi1;
                    *(uint32_t*)((char*)Cl + ((size_t)(r0 + 8) * N + col) * 2) = lo1;
                }
            }
        }
    }
}

// ---------------------------------------------------------------------------
// HMMA flash attention.
// grid (T/128, B*H); 256 threads (8 warps); warp w owns q-rows [16w,16w+16).
// Key tiles of 64; online softmax; P re-split; writes att as bf16 hi/lo.
// ---------------------------------------------------------------------------
__global__ __launch_bounds__(256, 2) void flash_hmma(
    const bf16* __restrict__ Qh, const bf16* __restrict__ Ql,
    const bf16* __restrict__ Kh, const bf16* __restrict__ Kl,
    const bf16* __restrict__ Vh, const bf16* __restrict__ Vl,
    bf16* __restrict__ Oh, bf16* __restrict__ Ol)
{
    extern __shared__ char sm[];
    constexpr uint32_t SQH = 0, SQL = 16384, SKH = 32768, SKL = 40960,
                       SVH = 49152, SVL = 57344;
    const int tid = threadIdx.x, wid = tid >> 5, lane = tid & 31;
    const int bh = blockIdx.y, b = bh >> 3, h = bh & 7;
    const int t0 = blockIdx.x * 128;
    const uint32_t sb = smem_u32(sm);

    // ---- stage Q (128 rows x 64 bf16, hi+lo)
    {
        int r = tid >> 1, c16 = (tid & 1) << 4;   // 128 rows x 2 sixteens? (32B/row)
        // 128 rows x 128B = 1024 uint4; 256 threads x 4
#pragma unroll
        for (int l = 0; l < 4; l++) {
            int idx = l * 256 + tid;
            int row = idx >> 3, cc = (idx & 7) << 4;
            uint32_t off = swz((uint32_t)row * 128u + (uint32_t)cc);
            size_t gq = (((size_t)(t0 + row) * B_ + b) * E_ + h * 64) * 2 + cc;
            *(uint4*)(sm + SQH + off) = *(const uint4*)((const char*)Qh + gq);
            *(uint4*)(sm + SQL + off) = *(const uint4*)((const char*)Ql + gq);
        }
        (void)r; (void)c16;
    }

    const int a_row = 16 * wid + (lane & 15);
    const int a_k   = (lane >> 4) * 8;
    const int b_n   = (lane & 7) + (lane >> 4) * 8;
    const int b_k   = ((lane >> 3) & 1) * 8;
    const int g = lane >> 2, t = lane & 3;

    float m_run[2] = {-1e30f, -1e30f}, l_run[2] = {0.f, 0.f};
    float o_acc[8][4];
#pragma unroll
    for (int j = 0; j < 8; j++)
#pragma unroll
        for (int r = 0; r < 4; r++) o_acc[j][r] = 0.f;

    for (int kt = 0; kt < CK_ / 64; kt++) {
        // ---- stage K,V tile (64 rows x 128B x 4 tensors)
#pragma unroll
        for (int l = 0; l < 2; l++) {
            int idx = l * 256 + tid;
            int row = idx >> 3, cc = (idx & 7) << 4;
            uint32_t off = swz((uint32_t)row * 128u + (uint32_t)cc);
            size_t gk = (((size_t)(kt * 64 + row) * B_ + b) * E_ + h * 64) * 2 + cc;
            *(uint4*)(sm + SKH + off) = *(const uint4*)((const char*)Kh + gk);
            *(uint4*)(sm + SKL + off) = *(const uint4*)((const char*)Kl + gk);
            *(uint4*)(sm + SVH + off) = *(const uint4*)((const char*)Vh + gk);
            *(uint4*)(sm + SVL + off) = *(const uint4*)((const char*)Vl + gk);
        }
        __syncthreads();

        // ---- S = Q·K^T (m16 x n64), 3-pass split
        float s[8][4];
#pragma unroll
        for (int j = 0; j < 8; j++)
#pragma unroll
            for (int r = 0; r < 4; r++) s[j][r] = 0.f;

#pragma unroll
        for (int pass = 0; pass < 3; pass++) {
            const uint32_t ab = sb + (pass == 2 ? SQL : SQH);
            const uint32_t bb = sb + (pass == 1 ? SKL : SKH);
#pragma unroll
            for (int ks = 0; ks < 4; ks++) {
                uint32_t af[4], bfr[4][4];
                uint32_t ad = ab + swz((uint32_t)a_row * 128u
                                       + (uint32_t)(ks * 16 + a_k) * 2u);
                LDSM_X4(af[0], af[1], af[2], af[3], ad);
#pragma unroll
                for (int nt = 0; nt < 4; nt++) {
                    uint32_t bd = bb + swz((uint32_t)(b_n + nt * 16) * 128u
                                           + (uint32_t)(ks * 16 + b_k) * 2u);
                    LDSM_X4(bfr[nt][0], bfr[nt][1], bfr[nt][2], bfr[nt][3], bd);
                }
#pragma unroll
                for (int n8 = 0; n8 < 8; n8++)
                    mma16816(s[n8], af, &bfr[n8 >> 1][(n8 & 1) * 2]);
            }
        }

        // ---- online softmax (rows g, g+8 of warp tile)
        float mn[2];
#pragma unroll
        for (int r = 0; r < 2; r++) {
            float v = -1e30f;
#pragma unroll
            for (int j = 0; j < 8; j++)
                v = fmaxf(v, fmaxf(s[j][r * 2], s[j][r * 2 + 1]));
            v = fmaxf(v, __shfl_xor_sync(0xffffffffu, v, 1));
            v = fmaxf(v, __shfl_xor_sync(0xffffffffu, v, 2));
            mn[r] = fmaxf(v, m_run[r]);
        }
        uint32_t ph2[8][2], pl2[8][2];
        float rs[2] = {0.f, 0.f};
#pragma unroll
        for (int j = 0; j < 8; j++) {
#pragma unroll
            for (int r = 0; r < 2; r++) {
                float p0 = __expf(s[j][r * 2]     - mn[r]);
                float p1 = __expf(s[j][r * 2 + 1] - mn[r]);
                rs[r] += p0 + p1;
                ph2[j][r] = pack_hi(p0, p1, pl2[j][r]);
            }
        }
#pragma unroll
        for (int r = 0; r < 2; r++) {
            float v = rs[r];
            v += __shfl_xor_sync(0xffffffffu, v, 1);
            v += __shfl_xor_sync(0xffffffffu, v, 2);
            float f = __expf(m_run[r] - mn[r]);
            l_run[r] = l_run[r] * f + v;
            m_run[r] = mn[r];
#pragma unroll
            for (int j = 0; j < 8; j++) {
                o_acc[j][r * 2]     *= f;
                o_acc[j][r * 2 + 1] *= f;
            }
        }

        // ---- O += P·V  (3 passes: Ph·Vh, Ph·Vl, Pl·Vh)
#pragma unroll
        for (int pass = 0; pass < 3; pass++) {
            const uint32_t vb = sb + (pass == 1 ? SVL : SVH);
            const uint32_t (*pa)[2] = (pass == 2) ? pl2 : ph2;
#pragma unroll
            for (int ks = 0; ks < 4; ks++) {
                uint32_t af[4] = {pa[2 * ks][0], pa[2 * ks][1],
                                  pa[2 * ks + 1][0], pa[2 * ks + 1][1]};
#pragma unroll
                for (int n8 = 0; n8 < 8; n8++) {
                    uint32_t b0, b1;
                    uint32_t vd = vb + swz((uint32_t)(ks * 16 + (lane & 15)) * 128u
                                           + (uint32_t)(n8 * 16));
                    LDSM_X2_T(b0, b1, vd);
                    uint32_t bv[2] = {b0, b1};
                    mma16816(o_acc[n8], af, bv);
                }
            }
        }
        __syncthreads();
    }

    // ---- normalize + write att as bf16 hi/lo
    float inv[2] = {1.f / l_run[0], 1.f / l_run[1]};
#pragma unroll
    for (int n8 = 0; n8 < 8; n8++) {
        int col = h * 64 + n8 * 8 + t * 2;
#pragma unroll
        for (int r = 0; r < 2; r++) {
            int row = t0 + 16 * wid + g + r * 8;
            float v0 = o_acc[n8][r * 2] * inv[r];
            float v1 = o_acc[n8][r * 2 + 1] * inv[r];
            uint32_t lo;
            uint32_t hi = pack_hi(v0, v1, lo);
            size_t off = (((size_t)row * B_ + b) * E_ + col) * 2;
            *(uint32_t*)((char*)Oh + off) = hi;
            *(uint32_t*)((char*)Ol + off) = lo;
        }
    }
}

// ---------------------------------------------------------------------------
extern "C" void kernel_launch(void* const* d_in, const int* in_sizes, int n_in,
                              void* d_out, int out_size)
{
    const float* query = (const float*)d_in[0];
    const float* Wq    = (const float*)d_in[1];
    const float* bq    = (const float*)d_in[2];
    const float* Wk    = (const float*)d_in[3];
    const float* bk    = (const float*)d_in[4];
    const float* Wv    = (const float*)d_in[5];
    const float* bv    = (const float*)d_in[6];
    const float* Wck   = (const float*)d_in[7];
    const float* Wcv   = (const float*)d_in[8];
    const float* Wo    = (const float*)d_in[9];
    const float* bo    = (const float*)d_in[10];
    float* out = (float*)d_out;

    float* part; cudaGetSymbolAddress((void**)&part, g_part);
    bf16 *xnth, *xntl, *xth, *xtl, *wqh, *wql, *wkh, *wkl, *wvh, *wvl, *woh, *wol;
    bf16 *wckh, *wckl, *wcvh, *wcvl, *qh, *ql, *kinh, *kinl, *vinh, *vinl;
    bf16 *kh, *kl, *vh, *vl, *atth, *attl;
    cudaGetSymbolAddress((void**)&xnth, g_xnth); cudaGetSymbolAddress((void**)&xntl, g_xntl);
    cudaGetSymbolAddress((void**)&xth,  g_xth);  cudaGetSymbolAddress((void**)&xtl,  g_xtl);
    cudaGetSymbolAddress((void**)&wqh,  g_wqh);  cudaGetSymbolAddress((void**)&wql,  g_wql);
    cudaGetSymbolAddress((void**)&wkh,  g_wkh);  cudaGetSymbolAddress((void**)&wkl,  g_wkl);
    cudaGetSymbolAddress((void**)&wvh,  g_wvh);  cudaGetSymbolAddress((void**)&wvl,  g_wvl);
    cudaGetSymbolAddress((void**)&woh,  g_woh);  cudaGetSymbolAddress((void**)&wol,  g_wol);
    cudaGetSymbolAddress((void**)&wckh, g_wckh); cudaGetSymbolAddress((void**)&wckl, g_wckl);
    cudaGetSymbolAddress((void**)&wcvh, g_wcvh); cudaGetSymbolAddress((void**)&wcvl, g_wcvl);
    cudaGetSymbolAddress((void**)&qh,   g_qh);   cudaGetSymbolAddress((void**)&ql,   g_ql);
    cudaGetSymbolAddress((void**)&kinh, g_kinh); cudaGetSymbolAddress((void**)&kinl, g_kinl);
    cudaGetSymbolAddress((void**)&vinh, g_vinh); cudaGetSymbolAddress((void**)&vinl, g_vinl);
    cudaGetSymbolAddress((void**)&kh,   g_kh);   cudaGetSymbolAddress((void**)&kl,   g_kl);
    cudaGetSymbolAddress((void**)&vh,   g_vh);   cudaGetSymbolAddress((void**)&vl,   g_vl);
    cudaGetSymbolAddress((void**)&atth, g_atth); cudaGetSymbolAddress((void**)&attl, g_attl);

    const int GSM = 65536;
    cudaFuncSetAttribute(hmma_ps<0>, cudaFuncAttributeMaxDynamicSharedMemorySize, GSM);
    cudaFuncSetAttribute(hmma_ps<1>, cudaFuncAttributeMaxDynamicSharedMemorySize, GSM);
    cudaFuncSetAttribute(hmma_ps<2>, cudaFuncAttributeMaxDynamicSharedMemorySize, GSM);
    cudaFuncSetAttribute(flash_hmma, cudaFuncAttributeMaxDynamicSharedMemorySize, GSM);

    // ---- one-time splits
    split_kernel<<<(E_*E_ + 255)/256, 256>>>(Wq, wqh, wql, E_*E_);
    split_kernel<<<(E_*E_ + 255)/256, 256>>>(Wk, wkh, wkl, E_*E_);
    split_kernel<<<(E_*E_ + 255)/256, 256>>>(Wv, wvh, wvl, E_*E_);
    split_kernel<<<(E_*E_ + 255)/256, 256>>>(Wo, woh, wol, E_*E_);
    split_kernel<<<(CK_*T_ + 255)/256, 256>>>(Wck, wckh, wckl, CK_*T_);
    split_kernel<<<(CK_*T_ + 255)/256, 256>>>(Wcv, wcvh, wcvl, CK_*T_);
    split_kernel<<<(T_*NB_ + 255)/256, 256>>>(query, xnth, xntl, T_*NB_);
    transpose_split_kernel<<<dim3(NB_/32, T_/32), 256>>>(query, xth, xtl);

    // 1) q = (X·Wq^T + bq)*0.125 -> split  [16384x512x512]
    hmma_ps<1><<<dim3(4, 128, 1), 256, GSM>>>(
        xnth, xntl, wqh, wql, bq, nullptr, qh, ql, T_*B_, E_, E_, E_, 0.125f);

    // 2) kin = Wck·X^T  (split-K 4)  [1024x2048x4096]
    hmma_ps<2><<<dim3(16, 8, 4), 256, GSM>>>(
        wckh, wckl, xth, xtl, nullptr, part, nullptr, nullptr, CK_, NB_, T_, 1024, 1.f);
    reduce_split_kernel<<<(CK_*NB_ + 255)/256, 256>>>(part, 4, nullptr, kinh, kinl, CK_*NB_, NB_);

    // 3) vin = Wcv·X^T
    hmma_ps<2><<<dim3(16, 8, 4), 256, GSM>>>(
        wcvh, wcvl, xth, xtl, nullptr, part, nullptr, nullptr, CK_, NB_, T_, 1024, 1.f);
    reduce_split_kernel<<<(CK_*NB_ + 255)/256, 256>>>(part, 4, nullptr, vinh, vinl, CK_*NB_, NB_);

    // 4) k = kin·Wk^T + bk  (split-K 2)  [4096x512x512]
    hmma_ps<2><<<dim3(4, 32, 2), 256, GSM>>>(
        kinh, kinl, wkh, wkl, nullptr, part, nullptr, nullptr, CK_*B_, E_, E_, 256, 1.f);
    reduce_split_kernel<<<(CK_*B_*E_ + 255)/256, 256>>>(part, 2, bk, kh, kl, CK_*B_*E_, E_);

    // 5) v = vin·Wv^T + bv
    hmma_ps<2><<<dim3(4, 32, 2), 256, GSM>>>(
        vinh, vinl, wvh, wvl, nullptr, part, nullptr, nullptr, CK_*B_, E_, E_, 256, 1.f);
    reduce_split_kernel<<<(CK_*B_*E_ + 255)/256, 256>>>(part, 2, bv, vh, vl, CK_*B_*E_, E_);

    // 6) flash attention -> att split
    flash_hmma<<<dim3(T_/128, B_*H_), 256, GSM>>>(qh, ql, kh, kl, vh, vl, atth, attl);

    // 7) out = att·Wo^T + bo  [16384x512x512]
    hmma_ps<0><<<dim3(4, 128, 1), 256, GSM>>>(
        atth, attl, woh, wol, bo, out, nullptr, nullptr, T_*B_, E_, E_, E_, 1.f);

    (void)in_sizes; (void)n_in; (void)out_size;
}

// round 5
// speedup vs baseline: 3.0432x; 1.3278x over previous
#include <cuda_runtime.h>
#include <cuda_bf16.h>
#include <math.h>
#include <cstdint>

// Problem constants
#define T_ 4096
#define B_ 4
#define E_ 512
#define CK_ 1024
#define H_ 8
#define HD_ 64
#define NB_ (B_ * E_)   // 2048

typedef __nv_bfloat16 bf16;

// ---------------- scratch (__device__ globals) ------------------------------
__device__ float g_part[(size_t)4 * CK_ * NB_];          // split-K partials (32MB)
__device__ bf16 g_xnth[(size_t)T_ * NB_],  g_xntl[(size_t)T_ * NB_];   // X   [16384][512]
__device__ bf16 g_xth [(size_t)NB_ * T_],  g_xtl [(size_t)NB_ * T_];   // X^T [2048][4096]
__device__ bf16 g_wqh[E_*E_], g_wql[E_*E_], g_wkh[E_*E_], g_wkl[E_*E_];
__device__ bf16 g_wvh[E_*E_], g_wvl[E_*E_], g_woh[E_*E_], g_wol[E_*E_];
__device__ bf16 g_wckh[(size_t)CK_*T_], g_wckl[(size_t)CK_*T_];
__device__ bf16 g_wcvh[(size_t)CK_*T_], g_wcvl[(size_t)CK_*T_];
__device__ bf16 g_qh [(size_t)T_*B_*E_],  g_ql [(size_t)T_*B_*E_];
__device__ bf16 g_kinh[(size_t)CK_*NB_],  g_kinl[(size_t)CK_*NB_];
__device__ bf16 g_vinh[(size_t)CK_*NB_],  g_vinl[(size_t)CK_*NB_];
__device__ bf16 g_kh [(size_t)CK_*B_*E_], g_kl [(size_t)CK_*B_*E_];
__device__ bf16 g_vh [(size_t)CK_*B_*E_], g_vl [(size_t)CK_*B_*E_];
__device__ bf16 g_atth[(size_t)T_*B_*E_], g_attl[(size_t)T_*B_*E_];

// ---------------- helpers ---------------------------------------------------
__device__ __forceinline__ uint32_t smem_u32(const void* p) {
    uint32_t a;
    asm("{ .reg .u64 t; cvta.to.shared.u64 t, %1; cvt.u32.u64 %0, t; }" : "=r"(a) : "l"(p));
    return a;
}
__device__ __forceinline__ uint32_t swz(uint32_t off) { return off ^ ((off >> 3) & 0x70); }

#define LDSM_X4(r0, r1, r2, r3, addr) \
    asm volatile("ldmatrix.sync.aligned.m8n8.x4.shared.b16 {%0,%1,%2,%3}, [%4];" \
        : "=r"(r0), "=r"(r1), "=r"(r2), "=r"(r3) : "r"(addr))
#define LDSM_X2_T(r0, r1, addr) \
    asm volatile("ldmatrix.sync.aligned.m8n8.x2.trans.shared.b16 {%0,%1}, [%2];" \
        : "=r"(r0), "=r"(r1) : "r"(addr))
#define CP_ASYNC16(dst, src) \
    asm volatile("cp.async.cg.shared.global [%0], [%1], 16;" :: "r"(dst), "l"(src))
#define CP_COMMIT() asm volatile("cp.async.commit_group;" ::: "memory")
#define CP_WAIT1()  asm volatile("cp.async.wait_group 1;" ::: "memory")
#define CP_WAIT0()  asm volatile("cp.async.wait_group 0;" ::: "memory")

__device__ __forceinline__ void mma16816(float* c, const uint32_t* a, const uint32_t* b) {
    asm volatile("mma.sync.aligned.m16n8k16.row.col.f32.bf16.bf16.f32 "
                 "{%0,%1,%2,%3}, {%4,%5,%6,%7}, {%8,%9}, {%0,%1,%2,%3};"
                 : "+f"(c[0]), "+f"(c[1]), "+f"(c[2]), "+f"(c[3])
                 : "r"(a[0]), "r"(a[1]), "r"(a[2]), "r"(a[3]), "r"(b[0]), "r"(b[1]));
}

__device__ __forceinline__ uint32_t pack_hi(float x0, float x1, uint32_t& lo) {
    bf16 h0 = __float2bfloat16(x0), h1 = __float2bfloat16(x1);
    bf16 l0 = __float2bfloat16(x0 - __bfloat162float(h0));
    bf16 l1 = __float2bfloat16(x1 - __bfloat162float(h1));
    lo = (uint32_t)__bfloat16_as_ushort(l0) | ((uint32_t)__bfloat16_as_ushort(l1) << 16);
    return (uint32_t)__bfloat16_as_ushort(h0) | ((uint32_t)__bfloat16_as_ushort(h1) << 16);
}

// ---------------------------------------------------------------------------
// Vectorized elementwise split: fp32 -> bf16 hi/lo (4 elem/thread)
// ---------------------------------------------------------------------------
__global__ void split4_kernel(const float4* __restrict__ src,
                              uint2* __restrict__ h, uint2* __restrict__ l, int n4)
{
    int i = blockIdx.x * blockDim.x + threadIdx.x;
    if (i < n4) {
        float4 x = src[i];
        uint32_t lo0, lo1;
        uint32_t hi0 = pack_hi(x.x, x.y, lo0);
        uint32_t hi1 = pack_hi(x.z, x.w, lo1);
        h[i] = make_uint2(hi0, hi1);
        l[i] = make_uint2(lo0, lo1);
    }
}

// Transpose + split: X[T][2048] fp32 -> Xt hi/lo [2048][T], vectorized I/O
__global__ __launch_bounds__(256) void transpose_split_kernel(
    const float* __restrict__ X, bf16* __restrict__ Xh, bf16* __restrict__ Xl)
{
    __shared__ float tile[32][36];
    int n0 = blockIdx.x * 32, t0 = blockIdx.y * 32;
    // load: 32 rows (t) x 32 cols (n) = 8 float4 per row; 256 thr = 32x8
    {
        int row = threadIdx.x >> 3, q = threadIdx.x & 7;
        float4 v = *(const float4*)(X + (size_t)(t0 + row) * NB_ + n0 + q * 4);
        tile[row][q * 4 + 0] = v.x; tile[row][q * 4 + 1] = v.y;
        tile[row][q * 4 + 2] = v.z; tile[row][q * 4 + 3] = v.w;
    }
    __syncthreads();
    // store: thread handles one n, 4 consecutive t
    {
        int n = threadIdx.x >> 3, tg = threadIdx.x & 7;
        float v0 = tile[tg * 4 + 0][n], v1 = tile[tg * 4 + 1][n];
        float v2 = tile[tg * 4 + 2][n], v3 = tile[tg * 4 + 3][n];
        uint32_t lo0, lo1;
        uint32_t hi0 = pack_hi(v0, v1, lo0);
        uint32_t hi1 = pack_hi(v2, v3, lo1);
        size_t o = ((size_t)(n0 + n) * T_ + t0 + tg * 4) * 2;
        *(uint2*)((char*)Xh + o) = make_uint2(hi0, hi1);
        *(uint2*)((char*)Xl + o) = make_uint2(lo0, lo1);
    }
}

// split-K reduce: sum S partials (+bias) -> bf16 hi/lo, 4 elem/thread
__global__ void reduce_split4_kernel(const float4* __restrict__ part, int S,
                                     const float* __restrict__ bias,
                                     uint2* __restrict__ Ch, uint2* __restrict__ Cl,
                                     int total4, int N)
{
    int i = blockIdx.x * blockDim.x + threadIdx.x;
    if (i >= total4) return;
    float4 s = part[i];
    for (int z = 1; z < S; z++) {
        float4 p = part[(size_t)z * total4 + i];
        s.x += p.x; s.y += p.y; s.z += p.z; s.w += p.w;
    }
    if (bias) {
        int col = (i * 4) % N;
        s.x += bias[col]; s.y += bias[col + 1]; s.z += bias[col + 2]; s.w += bias[col + 3];
    }
    uint32_t lo0, lo1;
    uint32_t hi0 = pack_hi(s.x, s.y, lo0);
    uint32_t hi1 = pack_hi(s.z, s.w, lo1);
    Ch[i] = make_uint2(hi0, hi1);
    Cl[i] = make_uint2(lo0, lo1);
}

// ---------------------------------------------------------------------------
// HMMA GEMM, pre-split bf16 hi/lo, K-major. C = A·B^T, 3-pass split.
// Tile 128x128, K-chunk 64, cp.async 2-stage double buffer (128KB smem).
// MODE 0: fp32 out +bias*scale | MODE 1: bf16 hi/lo out | MODE 2: split-K partial
// ---------------------------------------------------------------------------
template<int MODE>
__global__ __launch_bounds__(256, 1) void hmma_ps(
    const bf16* __restrict__ Ah_g, const bf16* __restrict__ Al_g,
    const bf16* __restrict__ Bh_g, const bf16* __restrict__ Bl_g,
    const float* __restrict__ bias, float* __restrict__ Cf,
    bf16* __restrict__ Ch, bf16* __restrict__ Cl,
    int M, int N, int K, int kps, float scale)
{
    extern __shared__ char sm[];
    constexpr uint32_t STG = 65536;             // per-stage stride
    constexpr uint32_t OAH = 0, OAL = 16384, OBH = 32768, OBL = 49152;
    const int tid = threadIdx.x, wid = tid >> 5, lane = tid & 31;
    const int warp_m = wid & 3, warp_n = wid >> 2;
    const int m0 = blockIdx.y * 128, n0 = blockIdx.x * 128;
    const int kz = blockIdx.z * kps;
    const uint32_t sb = smem_u32(sm);

    const int a_row = warp_m * 32 + (lane & 15);
    const int a_k   = (lane >> 4) * 8;
    const int b_n   = warp_n * 64 + (lane & 7) + (lane >> 4) * 8;
    const int b_k   = ((lane >> 3) & 1) * 8;
    const int st_row = tid >> 3, st_c16 = (tid & 7) << 4;

    float acc[2][8][4];
#pragma unroll
    for (int i = 0; i < 2; i++)
#pragma unroll
        for (int j = 0; j < 8; j++)
#pragma unroll
            for (int r = 0; r < 4; r++) acc[i][j][r] = 0.f;

    // stage chunk k0 into buffer buf (cp.async)
    auto stage = [&](int buf, int k0) {
        uint32_t base = sb + (uint32_t)buf * STG;
#pragma unroll
        for (int l = 0; l < 4; l++) {
            int row = st_row + l * 32;
            uint32_t off = swz((uint32_t)row * 128u + (uint32_t)st_c16);
            size_t ga = ((size_t)(m0 + row) * K + k0) * 2 + st_c16;
            size_t gb = ((size_t)(n0 + row) * K + k0) * 2 + st_c16;
            CP_ASYNC16(base + OAH + off, (const char*)Ah_g + ga);
            CP_ASYNC16(base + OAL + off, (const char*)Al_g + ga);
            CP_ASYNC16(base + OBH + off, (const char*)Bh_g + gb);
            CP_ASYNC16(base + OBL + off, (const char*)Bl_g + gb);
        }
    };

    const int nc = kps >> 6;
    stage(0, kz);
    CP_COMMIT();

    for (int kt = 0; kt < nc; kt++) {
        if (kt + 1 < nc) { stage((kt + 1) & 1, kz + (kt + 1) * 64); CP_COMMIT(); CP_WAIT1(); }
        else            { CP_WAIT0(); }
        __syncthreads();

        const uint32_t base = sb + (uint32_t)(kt & 1) * STG;
#pragma unroll
        for (int pass = 0; pass < 3; pass++) {
            const uint32_t ab = base + (pass == 2 ? OAL : OAH);
            const uint32_t bb = base + (pass == 1 ? OBL : OBH);
#pragma unroll
            for (int ks = 0; ks < 4; ks++) {
                uint32_t af[2][4], bfr[4][4];
#pragma unroll
                for (int mt = 0; mt < 2; mt++) {
                    uint32_t ad = ab + swz((uint32_t)(a_row + mt * 16) * 128u
                                           + (uint32_t)(ks * 16 + a_k) * 2u);
                    LDSM_X4(af[mt][0], af[mt][1], af[mt][2], af[mt][3], ad);
                }
#pragma unroll
                for (int nt = 0; nt < 4; nt++) {
                    uint32_t bd = bb + swz((uint32_t)(b_n + nt * 16) * 128u
                                           + (uint32_t)(ks * 16 + b_k) * 2u);
                    LDSM_X4(bfr[nt][0], bfr[nt][1], bfr[nt][2], bfr[nt][3], bd);
                }
#pragma unroll
                for (int mt = 0; mt < 2; mt++)
#pragma unroll
                    for (int n8 = 0; n8 < 8; n8++)
                        mma16816(acc[mt][n8], af[mt], &bfr[n8 >> 1][(n8 & 1) * 2]);
            }
        }
        __syncthreads();   // all warps done with this buffer before it is re-staged
    }

    // ---- epilogue
    const int g = lane >> 2, t = lane & 3;
#pragma unroll
    for (int mt = 0; mt < 2; mt++) {
        int r0 = m0 + warp_m * 32 + mt * 16 + g;
#pragma unroll
        for (int n8 = 0; n8 < 8; n8++) {
            int col = n0 + warp_n * 64 + n8 * 8 + t * 2;
            if (MODE == 2) {
                size_t base2 = (size_t)blockIdx.z * M * N;
                *(float2*)(Cf + base2 + (size_t)r0 * N + col) =
                    make_float2(acc[mt][n8][0], acc[mt][n8][1]);
                *(float2*)(Cf + base2 + (size_t)(r0 + 8) * N + col) =
                    make_float2(acc[mt][n8][2], acc[mt][n8][3]);
            } else {
                float b0 = bias ? bias[col] : 0.f, b1 = bias ? bias[col + 1] : 0.f;
                float v0 = (acc[mt][n8][0] + b0) * scale, v1 = (acc[mt][n8][1] + b1) * scale;
                float v2 = (acc[mt][n8][2] + b0) * scale, v3 = (acc[mt][n8][3] + b1) * scale;
                if (MODE == 0) {
                    *(float2*)(Cf + (size_t)r0 * N + col) = make_float2(v0, v1);
                    *(float2*)(Cf + (size_t)(r0 + 8) * N + col) = make_float2(v2, v3);
                } else {
                    uint32_t lo0, lo1;
                    uint32_t hi0 = pack_hi(v0, v1, lo0);
                    uint32_t hi1 = pack_hi(v2, v3, lo1);
                    *(uint32_t*)((char*)Ch + ((size_t)r0 * N + col) * 2) = hi0;
                    *(uint32_t*)((char*)Cl + ((size_t)r0 * N + col) * 2) = lo0;
                    *(uint32_t*)((char*)Ch + ((size_t)(r0 + 8) * N + col) * 2) = hi1;
                    *(uint32_t*)((char*)Cl + ((size_t)(r0 + 8) * N + col) * 2) = lo1;
                }
            }
        }
    }
}

// ---------------------------------------------------------------------------
// HMMA flash attention, cp.async double-buffered K/V.
// grid (T/128, B*H); 256 threads; warp w owns q-rows [16w,16w+16).
// smem: Q hi/lo 32KB + 2 x 32KB KV stages = 96KB -> 2 CTA/SM.
// ---------------------------------------------------------------------------
__global__ __launch_bounds__(256, 2) void flash_hmma(
    const bf16* __restrict__ Qh, const bf16* __restrict__ Ql,
    const bf16* __restrict__ Kh, const bf16* __restrict__ Kl,
    const bf16* __restrict__ Vh, const bf16* __restrict__ Vl,
    bf16* __restrict__ Oh, bf16* __restrict__ Ol)
{
    extern __shared__ char sm[];
    constexpr uint32_t SQH = 0, SQL = 16384, SKV = 32768, KSTG = 32768;
    constexpr uint32_t OKH = 0, OKL = 8192, OVH = 16384, OVL = 24576;
    const int tid = threadIdx.x, wid = tid >> 5, lane = tid & 31;
    const int bh = blockIdx.y, b = bh >> 3, h = bh & 7;
    const int t0 = blockIdx.x * 128;
    const uint32_t sb = smem_u32(sm);

    // ---- stage Q (plain stores; covered by first barrier)
#pragma unroll
    for (int l = 0; l < 4; l++) {
        int idx = l * 256 + tid;
        int row = idx >> 3, cc = (idx & 7) << 4;
        uint32_t off = swz((uint32_t)row * 128u + (uint32_t)cc);
        size_t gq = (((size_t)(t0 + row) * B_ + b) * E_ + h * 64) * 2 + cc;
        *(uint4*)(sm + SQH + off) = *(const uint4*)((const char*)Qh + gq);
        *(uint4*)(sm + SQL + off) = *(const uint4*)((const char*)Ql + gq);
    }

    auto stage_kv = [&](int buf, int kt) {
        uint32_t base = sb + SKV + (uint32_t)buf * KSTG;
#pragma unroll
        for (int l = 0; l < 2; l++) {
            int idx = l * 256 + tid;
            int row = idx >> 3, cc = (idx & 7) << 4;
            uint32_t off = swz((uint32_t)row * 128u + (uint32_t)cc);
            size_t gk = (((size_t)(kt * 64 + row) * B_ + b) * E_ + h * 64) * 2 + cc;
            CP_ASYNC16(base + OKH + off, (const char*)Kh + gk);
            CP_ASYNC16(base + OKL + off, (const char*)Kl + gk);
            CP_ASYNC16(base + OVH + off, (const char*)Vh + gk);
            CP_ASYNC16(base + OVL + off, (const char*)Vl + gk);
        }
    };

    const int a_row = 16 * wid + (lane & 15);
    const int a_k   = (lane >> 4) * 8;
    const int b_n   = (lane & 7) + (lane >> 4) * 8;
    const int b_k   = ((lane >> 3) & 1) * 8;
    const int g = lane >> 2, t = lane & 3;

    float m_run[2] = {-1e30f, -1e30f}, l_run[2] = {0.f, 0.f};
    float o_acc[8][4];
#pragma unroll
    for (int j = 0; j < 8; j++)
#pragma unroll
        for (int r = 0; r < 4; r++) o_acc[j][r] = 0.f;

    stage_kv(0, 0);
    CP_COMMIT();

    for (int kt = 0; kt < CK_ / 64; kt++) {
        if (kt + 1 < CK_ / 64) { stage_kv((kt + 1) & 1, kt + 1); CP_COMMIT(); CP_WAIT1(); }
        else                   { CP_WAIT0(); }
        __syncthreads();
        const uint32_t kvb = sb + SKV + (uint32_t)(kt & 1) * KSTG;

        // ---- S = Q·K^T (m16 x n64), 3-pass split
        float s[8][4];
#pragma unroll
        for (int j = 0; j < 8; j++)
#pragma unroll
            for (int r = 0; r < 4; r++) s[j][r] = 0.f;

#pragma unroll
        for (int pass = 0; pass < 3; pass++) {
            const uint32_t ab = sb + (pass == 2 ? SQL : SQH);
            const uint32_t bb = kvb + (pass == 1 ? OKL : OKH);
#pragma unroll
            for (int ks = 0; ks < 4; ks++) {
                uint32_t af[4], bfr[4][4];
                uint32_t ad = ab + swz((uint32_t)a_row * 128u
                                       + (uint32_t)(ks * 16 + a_k) * 2u);
                LDSM_X4(af[0], af[1], af[2], af[3], ad);
#pragma unroll
                for (int nt = 0; nt < 4; nt++) {
                    uint32_t bd = bb + swz((uint32_t)(b_n + nt * 16) * 128u
                                           + (uint32_t)(ks * 16 + b_k) * 2u);
                    LDSM_X4(bfr[nt][0], bfr[nt][1], bfr[nt][2], bfr[nt][3], bd);
                }
#pragma unroll
                for (int n8 = 0; n8 < 8; n8++)
                    mma16816(s[n8], af, &bfr[n8 >> 1][(n8 & 1) * 2]);
            }
        }

        // ---- online softmax (rows g, g+8 of warp tile)
        float mn[2];
#pragma unroll
        for (int r = 0; r < 2; r++) {
            float v = -1e30f;
#pragma unroll
            for (int j = 0; j < 8; j++)
                v = fmaxf(v, fmaxf(s[j][r * 2], s[j][r * 2 + 1]));
            v = fmaxf(v, __shfl_xor_sync(0xffffffffu, v, 1));
            v = fmaxf(v, __shfl_xor_sync(0xffffffffu, v, 2));
            mn[r] = fmaxf(v, m_run[r]);
        }
        uint32_t ph2[8][2], pl2[8][2];
        float rs[2] = {0.f, 0.f};
#pragma unroll
        for (int j = 0; j < 8; j++) {
#pragma unroll
            for (int r = 0; r < 2; r++) {
                float p0 = __expf(s[j][r * 2]     - mn[r]);
                float p1 = __expf(s[j][r * 2 + 1] - mn[r]);
                rs[r] += p0 + p1;
                ph2[j][r] = pack_hi(p0, p1, pl2[j][r]);
            }
        }
#pragma unroll
        for (int r = 0; r < 2; r++) {
            float v = rs[r];
            v += __shfl_xor_sync(0xffffffffu, v, 1);
            v += __shfl_xor_sync(0xffffffffu, v, 2);
            float f = __expf(m_run[r] - mn[r]);
            l_run[r] = l_run[r] * f + v;
            m_run[r] = mn[r];
#pragma unroll
            for (int j = 0; j < 8; j++) {
                o_acc[j][r * 2]     *= f;
                o_acc[j][r * 2 + 1] *= f;
            }
        }

        // ---- O += P·V  (3 passes: Ph·Vh, Ph·Vl, Pl·Vh)
#pragma unroll
        for (int pass = 0; pass < 3; pass++) {
            const uint32_t vb = kvb + (pass == 1 ? OVL : OVH);
            const uint32_t (*pa)[2] = (pass == 2) ? pl2 : ph2;
#pragma unroll
            for (int ks = 0; ks < 4; ks++) {
                uint32_t af[4] = {pa[2 * ks][0], pa[2 * ks][1],
                                  pa[2 * ks + 1][0], pa[2 * ks + 1][1]};
#pragma unroll
                for (int n8 = 0; n8 < 8; n8++) {
                    uint32_t b0, b1;
                    uint32_t vd = vb + swz((uint32_t)(ks * 16 + (lane & 15)) * 128u
                                           + (uint32_t)(n8 * 16));
                    LDSM_X2_T(b0, b1, vd);
                    uint32_t bv[2] = {b0, b1};
                    mma16816(o_acc[n8], af, bv);
                }
            }
        }
        __syncthreads();   // done reading this KV buffer
    }

    // ---- normalize + write att as bf16 hi/lo
    float inv[2] = {1.f / l_run[0], 1.f / l_run[1]};
#pragma unroll
    for (int n8 = 0; n8 < 8; n8++) {
        int col = h * 64 + n8 * 8 + t * 2;
#pragma unroll
        for (int r = 0; r < 2; r++) {
            int row = t0 + 16 * wid + g + r * 8;
            float v0 = o_acc[n8][r * 2] * inv[r];
            float v1 = o_acc[n8][r * 2 + 1] * inv[r];
            uint32_t lo;
            uint32_t hi = pack_hi(v0, v1, lo);
            size_t off = (((size_t)row * B_ + b) * E_ + col) * 2;
            *(uint32_t*)((char*)Oh + off) = hi;
            *(uint32_t*)((char*)Ol + off) = lo;
        }
    }
}

// ---------------------------------------------------------------------------
extern "C" void kernel_launch(void* const* d_in, const int* in_sizes, int n_in,
                              void* d_out, int out_size)
{
    const float* query = (const float*)d_in[0];
    const float* Wq    = (const float*)d_in[1];
    const float* bq    = (const float*)d_in[2];
    const float* Wk    = (const float*)d_in[3];
    const float* bk    = (const float*)d_in[4];
    const float* Wv    = (const float*)d_in[5];
    const float* bv    = (const float*)d_in[6];
    const float* Wck   = (const float*)d_in[7];
    const float* Wcv   = (const float*)d_in[8];
    const float* Wo    = (const float*)d_in[9];
    const float* bo    = (const float*)d_in[10];
    float* out = (float*)d_out;

    float* part; cudaGetSymbolAddress((void**)&part, g_part);
    bf16 *xnth, *xntl, *xth, *xtl, *wqh, *wql, *wkh, *wkl, *wvh, *wvl, *woh, *wol;
    bf16 *wckh, *wckl, *wcvh, *wcvl, *qh, *ql, *kinh, *kinl, *vinh, *vinl;
    bf16 *kh, *kl, *vh, *vl, *atth, *attl;
    cudaGetSymbolAddress((void**)&xnth, g_xnth); cudaGetSymbolAddress((void**)&xntl, g_xntl);
    cudaGetSymbolAddress((void**)&xth,  g_xth);  cudaGetSymbolAddress((void**)&xtl,  g_xtl);
    cudaGetSymbolAddress((void**)&wqh,  g_wqh);  cudaGetSymbolAddress((void**)&wql,  g_wql);
    cudaGetSymbolAddress((void**)&wkh,  g_wkh);  cudaGetSymbolAddress((void**)&wkl,  g_wkl);
    cudaGetSymbolAddress((void**)&wvh,  g_wvh);  cudaGetSymbolAddress((void**)&wvl,  g_wvl);
    cudaGetSymbolAddress((void**)&woh,  g_woh);  cudaGetSymbolAddress((void**)&wol,  g_wol);
    cudaGetSymbolAddress((void**)&wckh, g_wckh); cudaGetSymbolAddress((void**)&wckl, g_wckl);
    cudaGetSymbolAddress((void**)&wcvh, g_wcvh); cudaGetSymbolAddress((void**)&wcvl, g_wcvl);
    cudaGetSymbolAddress((void**)&qh,   g_qh);   cudaGetSymbolAddress((void**)&ql,   g_ql);
    cudaGetSymbolAddress((void**)&kinh, g_kinh); cudaGetSymbolAddress((void**)&kinl, g_kinl);
    cudaGetSymbolAddress((void**)&vinh, g_vinh); cudaGetSymbolAddress((void**)&vinl, g_vinl);
    cudaGetSymbolAddress((void**)&kh,   g_kh);   cudaGetSymbolAddress((void**)&kl,   g_kl);
    cudaGetSymbolAddress((void**)&vh,   g_vh);   cudaGetSymbolAddress((void**)&vl,   g_vl);
    cudaGetSymbolAddress((void**)&atth, g_atth); cudaGetSymbolAddress((void**)&attl, g_attl);

    const int GSM = 131072;   // 2-stage double buffer
    const int FSM = 98304;    // Q + 2 KV stages
    cudaFuncSetAttribute(hmma_ps<0>, cudaFuncAttributeMaxDynamicSharedMemorySize, GSM);
    cudaFuncSetAttribute(hmma_ps<1>, cudaFuncAttributeMaxDynamicSharedMemorySize, GSM);
    cudaFuncSetAttribute(hmma_ps<2>, cudaFuncAttributeMaxDynamicSharedMemorySize, GSM);
    cudaFuncSetAttribute(flash_hmma, cudaFuncAttributeMaxDynamicSharedMemorySize, FSM);

    // ---- one-time splits (vectorized)
    split4_kernel<<<(E_*E_/4 + 255)/256, 256>>>((const float4*)Wq, (uint2*)wqh, (uint2*)wql, E_*E_/4);
    split4_kernel<<<(E_*E_/4 + 255)/256, 256>>>((const float4*)Wk, (uint2*)wkh, (uint2*)wkl, E_*E_/4);
    split4_kernel<<<(E_*E_/4 + 255)/256, 256>>>((const float4*)Wv, (uint2*)wvh, (uint2*)wvl, E_*E_/4);
    split4_kernel<<<(E_*E_/4 + 255)/256, 256>>>((const float4*)Wo, (uint2*)woh, (uint2*)wol, E_*E_/4);
    split4_kernel<<<(CK_*T_/4 + 255)/256, 256>>>((const float4*)Wck, (uint2*)wckh, (uint2*)wckl, CK_*T_/4);
    split4_kernel<<<(CK_*T_/4 + 255)/256, 256>>>((const float4*)Wcv, (uint2*)wcvh, (uint2*)wcvl, CK_*T_/4);
    split4_kernel<<<(T_*NB_/4 + 255)/256, 256>>>((const float4*)query, (uint2*)xnth, (uint2*)xntl, T_*NB_/4);
    transpose_split_kernel<<<dim3(NB_/32, T_/32), 256>>>(query, xth, xtl);

    // 1) q = (X·Wq^T + bq)*0.125 -> split  [16384x512x512]
    hmma_ps<1><<<dim3(4, 128, 1), 256, GSM>>>(
        xnth, xntl, wqh, wql, bq, nullptr, qh, ql, T_*B_, E_, E_, E_, 0.125f);

    // 2) kin = Wck·X^T  (split-K 4)  [1024x2048x4096]
    hmma_ps<2><<<dim3(16, 8, 4), 256, GSM>>>(
        wckh, wckl, xth, xtl, nullptr, part, nullptr, nullptr, CK_, NB_, T_, 1024, 1.f);
    reduce_split4_kernel<<<(CK_*NB_/4 + 255)/256, 256>>>(
        (const float4*)part, 4, nullptr, (uint2*)kinh, (uint2*)kinl, CK_*NB_/4, NB_);

    // 3) vin = Wcv·X^T
    hmma_ps<2><<<dim3(16, 8, 4), 256, GSM>>>(
        wcvh, wcvl, xth, xtl, nullptr, part, nullptr, nullptr, CK_, NB_, T_, 1024, 1.f);
    reduce_split4_kernel<<<(CK_*NB_/4 + 255)/256, 256>>>(
        (const float4*)part, 4, nullptr, (uint2*)vinh, (uint2*)vinl, CK_*NB_/4, NB_);

    // 4) k = kin·Wk^T + bk  (split-K 2)  [4096x512x512]
    hmma_ps<2><<<dim3(4, 32, 2), 256, GSM>>>(
        kinh, kinl, wkh, wkl, nullptr, part, nullptr, nullptr, CK_*B_, E_, E_, 256, 1.f);
    reduce_split4_kernel<<<(CK_*B_*E_/4 + 255)/256, 256>>>(
        (const float4*)part, 2, bk, (uint2*)kh, (uint2*)kl, CK_*B_*E_/4, E_);

    // 5) v = vin·Wv^T + bv
    hmma_ps<2><<<dim3(4, 32, 2), 256, GSM>>>(
        vinh, vinl, wvh, wvl, nullptr, part, nullptr, nullptr, CK_*B_, E_, E_, 256, 1.f);
    reduce_split4_kernel<<<(CK_*B_*E_/4 + 255)/256, 256>>>(
        (const float4*)part, 2, bv, (uint2*)vh, (uint2*)vl, CK_*B_*E_/4, E_);

    // 6) flash attention -> att split
    flash_hmma<<<dim3(T_/128, B_*H_), 256, FSM>>>(qh, ql, kh, kl, vh, vl, atth, attl);

    // 7) out = att·Wo^T + bo  [16384x512x512]
    hmma_ps<0><<<dim3(4, 128, 1), 256, GSM>>>(
        atth, attl, woh, wol, bo, out, nullptr, nullptr, T_*B_, E_, E_, E_, 1.f);

    (void)in_sizes; (void)n_in; (void)out_size;
}

// round 6
// speedup vs baseline: 3.4973x; 1.1492x over previous
#include <cuda_runtime.h>
#include <cuda_bf16.h>
#include <math.h>
#include <cstdint>

// Problem constants
#define T_ 4096
#define B_ 4
#define E_ 512
#define CK_ 1024
#define H_ 8
#define HD_ 64
#define NB_ (B_ * E_)   // 2048

typedef __nv_bfloat16 bf16;

// ---------------- scratch (__device__ globals) ------------------------------
__device__ float g_part1[(size_t)4 * CK_ * NB_];         // s1-chain partials (32MB)
__device__ float g_part2[(size_t)4 * CK_ * NB_];         // s2-chain partials (32MB)
__device__ bf16 g_xnth[(size_t)T_ * NB_],  g_xntl[(size_t)T_ * NB_];   // X   [16384][512]
__device__ bf16 g_xth [(size_t)NB_ * T_],  g_xtl [(size_t)NB_ * T_];   // X^T [2048][4096]
__device__ bf16 g_wqh[E_*E_], g_wql[E_*E_], g_wkh[E_*E_], g_wkl[E_*E_];
__device__ bf16 g_wvh[E_*E_], g_wvl[E_*E_], g_woh[E_*E_], g_wol[E_*E_];
__device__ bf16 g_wckh[(size_t)CK_*T_], g_wckl[(size_t)CK_*T_];
__device__ bf16 g_wcvh[(size_t)CK_*T_], g_wcvl[(size_t)CK_*T_];
__device__ bf16 g_qh [(size_t)T_*B_*E_],  g_ql [(size_t)T_*B_*E_];
__device__ bf16 g_kinh[(size_t)CK_*NB_],  g_kinl[(size_t)CK_*NB_];
__device__ bf16 g_vinh[(size_t)CK_*NB_],  g_vinl[(size_t)CK_*NB_];
__device__ bf16 g_kh [(size_t)CK_*B_*E_], g_kl [(size_t)CK_*B_*E_];
__device__ bf16 g_vh [(size_t)CK_*B_*E_], g_vl [(size_t)CK_*B_*E_];
__device__ bf16 g_atth[(size_t)T_*B_*E_], g_attl[(size_t)T_*B_*E_];

// ---------------- helpers ---------------------------------------------------
__device__ __forceinline__ uint32_t smem_u32(const void* p) {
    uint32_t a;
    asm("{ .reg .u64 t; cvta.to.shared.u64 t, %1; cvt.u32.u64 %0, t; }" : "=r"(a) : "l"(p));
    return a;
}
__device__ __forceinline__ uint32_t swz(uint32_t off) { return off ^ ((off >> 3) & 0x70); }

#define LDSM_X4(r0, r1, r2, r3, addr) \
    asm volatile("ldmatrix.sync.aligned.m8n8.x4.shared.b16 {%0,%1,%2,%3}, [%4];" \
        : "=r"(r0), "=r"(r1), "=r"(r2), "=r"(r3) : "r"(addr))
#define LDSM_X2_T(r0, r1, addr) \
    asm volatile("ldmatrix.sync.aligned.m8n8.x2.trans.shared.b16 {%0,%1}, [%2];" \
        : "=r"(r0), "=r"(r1) : "r"(addr))
#define CP_ASYNC16(dst, src) \
    asm volatile("cp.async.cg.shared.global [%0], [%1], 16;" :: "r"(dst), "l"(src))
#define CP_COMMIT() asm volatile("cp.async.commit_group;" ::: "memory")
#define CP_WAIT1()  asm volatile("cp.async.wait_group 1;" ::: "memory")
#define CP_WAIT0()  asm volatile("cp.async.wait_group 0;" ::: "memory")

__device__ __forceinline__ void mma16816(float* c, const uint32_t* a, const uint32_t* b) {
    asm volatile("mma.sync.aligned.m16n8k16.row.col.f32.bf16.bf16.f32 "
                 "{%0,%1,%2,%3}, {%4,%5,%6,%7}, {%8,%9}, {%0,%1,%2,%3};"
                 : "+f"(c[0]), "+f"(c[1]), "+f"(c[2]), "+f"(c[3])
                 : "r"(a[0]), "r"(a[1]), "r"(a[2]), "r"(a[3]), "r"(b[0]), "r"(b[1]));
}

__device__ __forceinline__ uint32_t pack_hi(float x0, float x1, uint32_t& lo) {
    bf16 h0 = __float2bfloat16(x0), h1 = __float2bfloat16(x1);
    bf16 l0 = __float2bfloat16(x0 - __bfloat162float(h0));
    bf16 l1 = __float2bfloat16(x1 - __bfloat162float(h1));
    lo = (uint32_t)__bfloat16_as_ushort(l0) | ((uint32_t)__bfloat16_as_ushort(l1) << 16);
    return (uint32_t)__bfloat16_as_ushort(h0) | ((uint32_t)__bfloat16_as_ushort(h1) << 16);
}

// ---------------------------------------------------------------------------
// Batched elementwise split: 6 tensors in one launch (grid.y selects job)
// ---------------------------------------------------------------------------
struct SplitJobs {
    const float4* src[6];
    uint2* h[6];
    uint2* l[6];
    int n4[6];
};

__global__ void split_many(SplitJobs j)
{
    const int y = blockIdx.y;
    const float4* __restrict__ src = j.src[y];
    uint2* __restrict__ h = j.h[y];
    uint2* __restrict__ l = j.l[y];
    const int n4 = j.n4[y];
    for (int i = blockIdx.x * blockDim.x + threadIdx.x; i < n4;
         i += gridDim.x * blockDim.x) {
        float4 x = src[i];
        uint32_t lo0, lo1;
        uint32_t hi0 = pack_hi(x.x, x.y, lo0);
        uint32_t hi1 = pack_hi(x.z, x.w, lo1);
        h[i] = make_uint2(hi0, hi1);
        l[i] = make_uint2(lo0, lo1);
    }
}

// Fused query split: X[T][2048] fp32 -> normal hi/lo AND transposed hi/lo
__global__ __launch_bounds__(256) void splitq_kernel(
    const float* __restrict__ X,
    bf16* __restrict__ Xnh, bf16* __restrict__ Xnl,
    bf16* __restrict__ Xth, bf16* __restrict__ Xtl)
{
    __shared__ float tile[32][36];
    int n0 = blockIdx.x * 32, t0 = blockIdx.y * 32;
    // load + normal-order split
    {
        int row = threadIdx.x >> 3, q = threadIdx.x & 7;
        float4 v = *(const float4*)(X + (size_t)(t0 + row) * NB_ + n0 + q * 4);
        uint32_t lo0, lo1;
        uint32_t hi0 = pack_hi(v.x, v.y, lo0);
        uint32_t hi1 = pack_hi(v.z, v.w, lo1);
        size_t on = ((size_t)(t0 + row) * NB_ + n0 + q * 4) * 2;
        *(uint2*)((char*)Xnh + on) = make_uint2(hi0, hi1);
        *(uint2*)((char*)Xnl + on) = make_uint2(lo0, lo1);
        tile[row][q * 4 + 0] = v.x; tile[row][q * 4 + 1] = v.y;
        tile[row][q * 4 + 2] = v.z; tile[row][q * 4 + 3] = v.w;
    }
    __syncthreads();
    // transposed split
    {
        int n = threadIdx.x >> 3, tg = threadIdx.x & 7;
        float v0 = tile[tg * 4 + 0][n], v1 = tile[tg * 4 + 1][n];
        float v2 = tile[tg * 4 + 2][n], v3 = tile[tg * 4 + 3][n];
        uint32_t lo0, lo1;
        uint32_t hi0 = pack_hi(v0, v1, lo0);
        uint32_t hi1 = pack_hi(v2, v3, lo1);
        size_t o = ((size_t)(n0 + n) * T_ + t0 + tg * 4) * 2;
        *(uint2*)((char*)Xth + o) = make_uint2(hi0, hi1);
        *(uint2*)((char*)Xtl + o) = make_uint2(lo0, lo1);
    }
}

// split-K reduce: sum S partials (+bias) -> bf16 hi/lo, 4 elem/thread
__global__ void reduce_split4_kernel(const float4* __restrict__ part, int S,
                                     const float* __restrict__ bias,
                                     uint2* __restrict__ Ch, uint2* __restrict__ Cl,
                                     int total4, int N)
{
    int i = blockIdx.x * blockDim.x + threadIdx.x;
    if (i >= total4) return;
    float4 s = part[i];
    for (int z = 1; z < S; z++) {
        float4 p = part[(size_t)z * total4 + i];
        s.x += p.x; s.y += p.y; s.z += p.z; s.w += p.w;
    }
    if (bias) {
        int col = (i * 4) % N;
        s.x += bias[col]; s.y += bias[col + 1]; s.z += bias[col + 2]; s.w += bias[col + 3];
    }
    uint32_t lo0, lo1;
    uint32_t hi0 = pack_hi(s.x, s.y, lo0);
    uint32_t hi1 = pack_hi(s.z, s.w, lo1);
    Ch[i] = make_uint2(hi0, hi1);
    Cl[i] = make_uint2(lo0, lo1);
}

// ---------------------------------------------------------------------------
// HMMA GEMM, pre-split bf16 hi/lo, K-major. C = A·B^T, 3-pass split with
// hoisted hi/lo fragments (12 LDSM per k16-step feeding 48 MMAs).
// Tile 128x128, K-chunk 64, cp.async 2-stage double buffer (128KB smem).
// MODE 0: fp32 out +bias*scale | MODE 1: bf16 hi/lo out | MODE 2: split-K partial
// ---------------------------------------------------------------------------
template<int MODE>
__global__ __launch_bounds__(256, 1) void hmma_ps(
    const bf16* __restrict__ Ah_g, const bf16* __restrict__ Al_g,
    const bf16* __restrict__ Bh_g, const bf16* __restrict__ Bl_g,
    const float* __restrict__ bias, float* __restrict__ Cf,
    bf16* __restrict__ Ch, bf16* __restrict__ Cl,
    int M, int N, int K, int kps, float scale)
{
    extern __shared__ char sm[];
    constexpr uint32_t STG = 65536;             // per-stage stride
    constexpr uint32_t OAH = 0, OAL = 16384, OBH = 32768, OBL = 49152;
    const int tid = threadIdx.x, wid = tid >> 5, lane = tid & 31;
    const int warp_m = wid & 3, warp_n = wid >> 2;
    const int m0 = blockIdx.y * 128, n0 = blockIdx.x * 128;
    const int kz = blockIdx.z * kps;
    const uint32_t sb = smem_u32(sm);

    const int a_row = warp_m * 32 + (lane & 15);
    const int a_k   = (lane >> 4) * 8;
    const int b_n   = warp_n * 64 + (lane & 7) + (lane >> 4) * 8;
    const int b_k   = ((lane >> 3) & 1) * 8;
    const int st_row = tid >> 3, st_c16 = (tid & 7) << 4;

    float acc[2][8][4];
#pragma unroll
    for (int i = 0; i < 2; i++)
#pragma unroll
        for (int j = 0; j < 8; j++)
#pragma unroll
            for (int r = 0; r < 4; r++) acc[i][j][r] = 0.f;

    auto stage = [&](int buf, int k0) {
        uint32_t base = sb + (uint32_t)buf * STG;
#pragma unroll
        for (int l = 0; l < 4; l++) {
            int row = st_row + l * 32;
            uint32_t off = swz((uint32_t)row * 128u + (uint32_t)st_c16);
            size_t ga = ((size_t)(m0 + row) * K + k0) * 2 + st_c16;
            size_t gb = ((size_t)(n0 + row) * K + k0) * 2 + st_c16;
            CP_ASYNC16(base + OAH + off, (const char*)Ah_g + ga);
            CP_ASYNC16(base + OAL + off, (const char*)Al_g + ga);
            CP_ASYNC16(base + OBH + off, (const char*)Bh_g + gb);
            CP_ASYNC16(base + OBL + off, (const char*)Bl_g + gb);
        }
    };

    const int nc = kps >> 6;
    stage(0, kz);
    CP_COMMIT();

    for (int kt = 0; kt < nc; kt++) {
        if (kt + 1 < nc) { stage((kt + 1) & 1, kz + (kt + 1) * 64); CP_COMMIT(); CP_WAIT1(); }
        else            { CP_WAIT0(); }
        __syncthreads();

        const uint32_t base = sb + (uint32_t)(kt & 1) * STG;
#pragma unroll
        for (int ks = 0; ks < 4; ks++) {
            // hoisted fragment loads: hi+lo for A and B once per k16-step
            uint32_t afh[2][4], afl[2][4], bfh[4][4], bfl[4][4];
#pragma unroll
            for (int mt = 0; mt < 2; mt++) {
                uint32_t off = swz((uint32_t)(a_row + mt * 16) * 128u
                                   + (uint32_t)(ks * 16 + a_k) * 2u);
                LDSM_X4(afh[mt][0], afh[mt][1], afh[mt][2], afh[mt][3], base + OAH + off);
                LDSM_X4(afl[mt][0], afl[mt][1], afl[mt][2], afl[mt][3], base + OAL + off);
            }
#pragma unroll
            for (int nt = 0; nt < 4; nt++) {
                uint32_t off = swz((uint32_t)(b_n + nt * 16) * 128u
                                   + (uint32_t)(ks * 16 + b_k) * 2u);
                LDSM_X4(bfh[nt][0], bfh[nt][1], bfh[nt][2], bfh[nt][3], base + OBH + off);
                LDSM_X4(bfl[nt][0], bfl[nt][1], bfl[nt][2], bfl[nt][3], base + OBL + off);
            }
            // 3 pure-MMA passes: Ah·Bh, Ah·Bl, Al·Bh
#pragma unroll
            for (int mt = 0; mt < 2; mt++)
#pragma unroll
                for (int n8 = 0; n8 < 8; n8++)
                    mma16816(acc[mt][n8], afh[mt], &bfh[n8 >> 1][(n8 & 1) * 2]);
#pragma unroll
            for (int mt = 0; mt < 2; mt++)
#pragma unroll
                for (int n8 = 0; n8 < 8; n8++)
                    mma16816(acc[mt][n8], afh[mt], &bfl[n8 >> 1][(n8 & 1) * 2]);
#pragma unroll
            for (int mt = 0; mt < 2; mt++)
#pragma unroll
                for (int n8 = 0; n8 < 8; n8++)
                    mma16816(acc[mt][n8], afl[mt], &bfh[n8 >> 1][(n8 & 1) * 2]);
        }
        __syncthreads();
    }

    // ---- epilogue
    const int g = lane >> 2, t = lane & 3;
#pragma unroll
    for (int mt = 0; mt < 2; mt++) {
        int r0 = m0 + warp_m * 32 + mt * 16 + g;
#pragma unroll
        for (int n8 = 0; n8 < 8; n8++) {
            int col = n0 + warp_n * 64 + n8 * 8 + t * 2;
            if (MODE == 2) {
                size_t base2 = (size_t)blockIdx.z * M * N;
                *(float2*)(Cf + base2 + (size_t)r0 * N + col) =
                    make_float2(acc[mt][n8][0], acc[mt][n8][1]);
                *(float2*)(Cf + base2 + (size_t)(r0 + 8) * N + col) =
                    make_float2(acc[mt][n8][2], acc[mt][n8][3]);
            } else {
                float b0 = bias ? bias[col] : 0.f, b1 = bias ? bias[col + 1] : 0.f;
                float v0 = (acc[mt][n8][0] + b0) * scale, v1 = (acc[mt][n8][1] + b1) * scale;
                float v2 = (acc[mt][n8][2] + b0) * scale, v3 = (acc[mt][n8][3] + b1) * scale;
                if (MODE == 0) {
                    *(float2*)(Cf + (size_t)r0 * N + col) = make_float2(v0, v1);
                    *(float2*)(Cf + (size_t)(r0 + 8) * N + col) = make_float2(v2, v3);
                } else {
                    uint32_t lo0, lo1;
                    uint32_t hi0 = pack_hi(v0, v1, lo0);
                    uint32_t hi1 = pack_hi(v2, v3, lo1);
                    *(uint32_t*)((char*)Ch + ((size_t)r0 * N + col) * 2) = hi0;
                    *(uint32_t*)((char*)Cl + ((size_t)r0 * N + col) * 2) = lo0;
                    *(uint32_t*)((char*)Ch + ((size_t)(r0 + 8) * N + col) * 2) = hi1;
                    *(uint32_t*)((char*)Cl + ((size_t)(r0 + 8) * N + col) * 2) = lo1;
                }
            }
        }
    }
}

// ---------------------------------------------------------------------------
// HMMA flash attention, cp.async double-buffered K/V (unchanged from R5).
// ---------------------------------------------------------------------------
__global__ __launch_bounds__(256, 2) void flash_hmma(
    const bf16* __restrict__ Qh, const bf16* __restrict__ Ql,
    const bf16* __restrict__ Kh, const bf16* __restrict__ Kl,
    const bf16* __restrict__ Vh, const bf16* __restrict__ Vl,
    bf16* __restrict__ Oh, bf16* __restrict__ Ol)
{
    extern __shared__ char sm[];
    constexpr uint32_t SQH = 0, SQL = 16384, SKV = 32768, KSTG = 32768;
    constexpr uint32_t OKH = 0, OKL = 8192, OVH = 16384, OVL = 24576;
    const int tid = threadIdx.x, wid = tid >> 5, lane = tid & 31;
    const int bh = blockIdx.y, b = bh >> 3, h = bh & 7;
    const int t0 = blockIdx.x * 128;
    const uint32_t sb = smem_u32(sm);

#pragma unroll
    for (int l = 0; l < 4; l++) {
        int idx = l * 256 + tid;
        int row = idx >> 3, cc = (idx & 7) << 4;
        uint32_t off = swz((uint32_t)row * 128u + (uint32_t)cc);
        size_t gq = (((size_t)(t0 + row) * B_ + b) * E_ + h * 64) * 2 + cc;
        *(uint4*)(sm + SQH + off) = *(const uint4*)((const char*)Qh + gq);
        *(uint4*)(sm + SQL + off) = *(const uint4*)((const char*)Ql + gq);
    }

    auto stage_kv = [&](int buf, int kt) {
        uint32_t base = sb + SKV + (uint32_t)buf * KSTG;
#pragma unroll
        for (int l = 0; l < 2; l++) {
            int idx = l * 256 + tid;
            int row = idx >> 3, cc = (idx & 7) << 4;
            uint32_t off = swz((uint32_t)row * 128u + (uint32_t)cc);
            size_t gk = (((size_t)(kt * 64 + row) * B_ + b) * E_ + h * 64) * 2 + cc;
            CP_ASYNC16(base + OKH + off, (const char*)Kh + gk);
            CP_ASYNC16(base + OKL + off, (const char*)Kl + gk);
            CP_ASYNC16(base + OVH + off, (const char*)Vh + gk);
            CP_ASYNC16(base + OVL + off, (const char*)Vl + gk);
        }
    };

    const int a_row = 16 * wid + (lane & 15);
    const int a_k   = (lane >> 4) * 8;
    const int b_n   = (lane & 7) + (lane >> 4) * 8;
    const int b_k   = ((lane >> 3) & 1) * 8;
    const int g = lane >> 2, t = lane & 3;

    float m_run[2] = {-1e30f, -1e30f}, l_run[2] = {0.f, 0.f};
    float o_acc[8][4];
#pragma unroll
    for (int j = 0; j < 8; j++)
#pragma unroll
        for (int r = 0; r < 4; r++) o_acc[j][r] = 0.f;

    stage_kv(0, 0);
    CP_COMMIT();

    for (int kt = 0; kt < CK_ / 64; kt++) {
        if (kt + 1 < CK_ / 64) { stage_kv((kt + 1) & 1, kt + 1); CP_COMMIT(); CP_WAIT1(); }
        else                   { CP_WAIT0(); }
        __syncthreads();
        const uint32_t kvb = sb + SKV + (uint32_t)(kt & 1) * KSTG;

        float s[8][4];
#pragma unroll
        for (int j = 0; j < 8; j++)
#pragma unroll
            for (int r = 0; r < 4; r++) s[j][r] = 0.f;

#pragma unroll
        for (int pass = 0; pass < 3; pass++) {
            const uint32_t ab = sb + (pass == 2 ? SQL : SQH);
            const uint32_t bb = kvb + (pass == 1 ? OKL : OKH);
#pragma unroll
            for (int ks = 0; ks < 4; ks++) {
                uint32_t af[4], bfr[4][4];
                uint32_t ad = ab + swz((uint32_t)a_row * 128u
                                       + (uint32_t)(ks * 16 + a_k) * 2u);
                LDSM_X4(af[0], af[1], af[2], af[3], ad);
#pragma unroll
                for (int nt = 0; nt < 4; nt++) {
                    uint32_t bd = bb + swz((uint32_t)(b_n + nt * 16) * 128u
                                           + (uint32_t)(ks * 16 + b_k) * 2u);
                    LDSM_X4(bfr[nt][0], bfr[nt][1], bfr[nt][2], bfr[nt][3], bd);
                }
#pragma unroll
                for (int n8 = 0; n8 < 8; n8++)
                    mma16816(s[n8], af, &bfr[n8 >> 1][(n8 & 1) * 2]);
            }
        }

        float mn[2];
#pragma unroll
        for (int r = 0; r < 2; r++) {
            float v = -1e30f;
#pragma unroll
            for (int j = 0; j < 8; j++)
                v = fmaxf(v, fmaxf(s[j][r * 2], s[j][r * 2 + 1]));
            v = fmaxf(v, __shfl_xor_sync(0xffffffffu, v, 1));
            v = fmaxf(v, __shfl_xor_sync(0xffffffffu, v, 2));
            mn[r] = fmaxf(v, m_run[r]);
        }
        uint32_t ph2[8][2], pl2[8][2];
        float rs[2] = {0.f, 0.f};
#pragma unroll
        for (int j = 0; j < 8; j++) {
#pragma unroll
            for (int r = 0; r < 2; r++) {
                float p0 = __expf(s[j][r * 2]     - mn[r]);
                float p1 = __expf(s[j][r * 2 + 1] - mn[r]);
                rs[r] += p0 + p1;
                ph2[j][r] = pack_hi(p0, p1, pl2[j][r]);
            }
        }
#pragma unroll
        for (int r = 0; r < 2; r++) {
            float v = rs[r];
            v += __shfl_xor_sync(0xffffffffu, v, 1);
            v += __shfl_xor_sync(0xffffffffu, v, 2);
            float f = __expf(m_run[r] - mn[r]);
            l_run[r] = l_run[r] * f + v;
            m_run[r] = mn[r];
#pragma unroll
            for (int j = 0; j < 8; j++) {
                o_acc[j][r * 2]     *= f;
                o_acc[j][r * 2 + 1] *= f;
            }
        }

#pragma unroll
        for (int pass = 0; pass < 3; pass++) {
            const uint32_t vb = kvb + (pass == 1 ? OVL : OVH);
            const uint32_t (*pa)[2] = (pass == 2) ? pl2 : ph2;
#pragma unroll
            for (int ks = 0; ks < 4; ks++) {
                uint32_t af[4] = {pa[2 * ks][0], pa[2 * ks][1],
                                  pa[2 * ks + 1][0], pa[2 * ks + 1][1]};
#pragma unroll
                for (int n8 = 0; n8 < 8; n8++) {
                    uint32_t b0, b1;
                    uint32_t vd = vb + swz((uint32_t)(ks * 16 + (lane & 15)) * 128u
                                           + (uint32_t)(n8 * 16));
                    LDSM_X2_T(b0, b1, vd);
                    uint32_t bv[2] = {b0, b1};
                    mma16816(o_acc[n8], af, bv);
                }
            }
        }
        __syncthreads();
    }

    float inv[2] = {1.f / l_run[0], 1.f / l_run[1]};
#pragma unroll
    for (int n8 = 0; n8 < 8; n8++) {
        int col = h * 64 + n8 * 8 + t * 2;
#pragma unroll
        for (int r = 0; r < 2; r++) {
            int row = t0 + 16 * wid + g + r * 8;
            float v0 = o_acc[n8][r * 2] * inv[r];
            float v1 = o_acc[n8][r * 2 + 1] * inv[r];
            uint32_t lo;
            uint32_t hi = pack_hi(v0, v1, lo);
            size_t off = (((size_t)row * B_ + b) * E_ + col) * 2;
            *(uint32_t*)((char*)Oh + off) = hi;
            *(uint32_t*)((char*)Ol + off) = lo;
        }
    }
}

// ---------------------------------------------------------------------------
extern "C" void kernel_launch(void* const* d_in, const int* in_sizes, int n_in,
                              void* d_out, int out_size)
{
    const float* query = (const float*)d_in[0];
    const float* Wq    = (const float*)d_in[1];
    const float* bq    = (const float*)d_in[2];
    const float* Wk    = (const float*)d_in[3];
    const float* bk    = (const float*)d_in[4];
    const float* Wv    = (const float*)d_in[5];
    const float* bv    = (const float*)d_in[6];
    const float* Wck   = (const float*)d_in[7];
    const float* Wcv   = (const float*)d_in[8];
    const float* Wo    = (const float*)d_in[9];
    const float* bo    = (const float*)d_in[10];
    float* out = (float*)d_out;

    float *part1, *part2;
    cudaGetSymbolAddress((void**)&part1, g_part1);
    cudaGetSymbolAddress((void**)&part2, g_part2);
    bf16 *xnth, *xntl, *xth, *xtl, *wqh, *wql, *wkh, *wkl, *wvh, *wvl, *woh, *wol;
    bf16 *wckh, *wckl, *wcvh, *wcvl, *qh, *ql, *kinh, *kinl, *vinh, *vinl;
    bf16 *kh, *kl, *vh, *vl, *atth, *attl;
    cudaGetSymbolAddress((void**)&xnth, g_xnth); cudaGetSymbolAddress((void**)&xntl, g_xntl);
    cudaGetSymbolAddress((void**)&xth,  g_xth);  cudaGetSymbolAddress((void**)&xtl,  g_xtl);
    cudaGetSymbolAddress((void**)&wqh,  g_wqh);  cudaGetSymbolAddress((void**)&wql,  g_wql);
    cudaGetSymbolAddress((void**)&wkh,  g_wkh);  cudaGetSymbolAddress((void**)&wkl,  g_wkl);
    cudaGetSymbolAddress((void**)&wvh,  g_wvh);  cudaGetSymbolAddress((void**)&wvl,  g_wvl);
    cudaGetSymbolAddress((void**)&woh,  g_woh);  cudaGetSymbolAddress((void**)&wol,  g_wol);
    cudaGetSymbolAddress((void**)&wckh, g_wckh); cudaGetSymbolAddress((void**)&wckl, g_wckl);
    cudaGetSymbolAddress((void**)&wcvh, g_wcvh); cudaGetSymbolAddress((void**)&wcvl, g_wcvl);
    cudaGetSymbolAddress((void**)&qh,   g_qh);   cudaGetSymbolAddress((void**)&ql,   g_ql);
    cudaGetSymbolAddress((void**)&kinh, g_kinh); cudaGetSymbolAddress((void**)&kinl, g_kinl);
    cudaGetSymbolAddress((void**)&vinh, g_vinh); cudaGetSymbolAddress((void**)&vinl, g_vinl);
    cudaGetSymbolAddress((void**)&kh,   g_kh);   cudaGetSymbolAddress((void**)&kl,   g_kl);
    cudaGetSymbolAddress((void**)&vh,   g_vh);   cudaGetSymbolAddress((void**)&vl,   g_vl);
    cudaGetSymbolAddress((void**)&atth, g_atth); cudaGetSymbolAddress((void**)&attl, g_attl);

    // one-time stream/event setup (first call is the uncaptured correctness
    // run; captured calls reuse the same handles — identical work every call)
    static cudaStream_t s1 = nullptr, s2 = nullptr;
    static cudaEvent_t eR = nullptr, e1 = nullptr, e2 = nullptr;
    if (!s1) {
        cudaStreamCreateWithFlags(&s1, cudaStreamNonBlocking);
        cudaStreamCreateWithFlags(&s2, cudaStreamNonBlocking);
        cudaEventCreateWithFlags(&eR, cudaEventDisableTiming);
        cudaEventCreateWithFlags(&e1, cudaEventDisableTiming);
        cudaEventCreateWithFlags(&e2, cudaEventDisableTiming);
    }

    const int GSM = 131072;   // 2-stage double buffer
    const int FSM = 98304;    // Q + 2 KV stages
    cudaFuncSetAttribute(hmma_ps<0>, cudaFuncAttributeMaxDynamicSharedMemorySize, GSM);
    cudaFuncSetAttribute(hmma_ps<1>, cudaFuncAttributeMaxDynamicSharedMemorySize, GSM);
    cudaFuncSetAttribute(hmma_ps<2>, cudaFuncAttributeMaxDynamicSharedMemorySize, GSM);
    cudaFuncSetAttribute(flash_hmma, cudaFuncAttributeMaxDynamicSharedMemorySize, FSM);

    // ---- elementwise splits (2 launches on s0)
    SplitJobs jobs;
    jobs.src[0] = (const float4*)Wq;  jobs.h[0] = (uint2*)wqh;  jobs.l[0] = (uint2*)wql;  jobs.n4[0] = E_*E_/4;
    jobs.src[1] = (const float4*)Wk;  jobs.h[1] = (uint2*)wkh;  jobs.l[1] = (uint2*)wkl;  jobs.n4[1] = E_*E_/4;
    jobs.src[2] = (const float4*)Wv;  jobs.h[2] = (uint2*)wvh;  jobs.l[2] = (uint2*)wvl;  jobs.n4[2] = E_*E_/4;
    jobs.src[3] = (const float4*)Wo;  jobs.h[3] = (uint2*)woh;  jobs.l[3] = (uint2*)wol;  jobs.n4[3] = E_*E_/4;
    jobs.src[4] = (const float4*)Wck; jobs.h[4] = (uint2*)wckh; jobs.l[4] = (uint2*)wckl; jobs.n4[4] = CK_*T_/4;
    jobs.src[5] = (const float4*)Wcv; jobs.h[5] = (uint2*)wcvh; jobs.l[5] = (uint2*)wcvl; jobs.n4[5] = CK_*T_/4;
    split_many<<<dim3(512, 6), 256>>>(jobs);
    splitq_kernel<<<dim3(NB_/32, T_/32), 256>>>(query, xnth, xntl, xth, xtl);

    // fork
    cudaEventRecord(eR, 0);
    cudaStreamWaitEvent(s1, eR, 0);
    cudaStreamWaitEvent(s2, eR, 0);

    // s0: q = (X·Wq^T + bq)*0.125 -> split  [16384x512x512]
    hmma_ps<1><<<dim3(4, 128, 1), 256, GSM>>>(
        xnth, xntl, wqh, wql, bq, nullptr, qh, ql, T_*B_, E_, E_, E_, 0.125f);

    // s1: kin = Wck·X^T (split-K 4) -> k = kin·Wk^T + bk (split-K 2)
    hmma_ps<2><<<dim3(16, 8, 4), 256, GSM, s1>>>(
        wckh, wckl, xth, xtl, nullptr, part1, nullptr, nullptr, CK_, NB_, T_, 1024, 1.f);
    reduce_split4_kernel<<<(CK_*NB_/4 + 255)/256, 256, 0, s1>>>(
        (const float4*)part1, 4, nullptr, (uint2*)kinh, (uint2*)kinl, CK_*NB_/4, NB_);
    hmma_ps<2><<<dim3(4, 32, 2), 256, GSM, s1>>>(
        kinh, kinl, wkh, wkl, nullptr, part1, nullptr, nullptr, CK_*B_, E_, E_, 256, 1.f);
    reduce_split4_kernel<<<(CK_*B_*E_/4 + 255)/256, 256, 0, s1>>>(
        (const float4*)part1, 2, bk, (uint2*)kh, (uint2*)kl, CK_*B_*E_/4, E_);
    cudaEventRecord(e1, s1);

    // s2: vin = Wcv·X^T (split-K 4) -> v = vin·Wv^T + bv (split-K 2)
    hmma_ps<2><<<dim3(16, 8, 4), 256, GSM, s2>>>(
        wcvh, wcvl, xth, xtl, nullptr, part2, nullptr, nullptr, CK_, NB_, T_, 1024, 1.f);
    reduce_split4_kernel<<<(CK_*NB_/4 + 255)/256, 256, 0, s2>>>(
        (const float4*)part2, 4, nullptr, (uint2*)vinh, (uint2*)vinl, CK_*NB_/4, NB_);
    hmma_ps<2><<<dim3(4, 32, 2), 256, GSM, s2>>>(
        vinh, vinl, wvh, wvl, nullptr, part2, nullptr, nullptr, CK_*B_, E_, E_, 256, 1.f);
    reduce_split4_kernel<<<(CK_*B_*E_/4 + 255)/256, 256, 0, s2>>>(
        (const float4*)part2, 2, bv, (uint2*)vh, (uint2*)vl, CK_*B_*E_/4, E_);
    cudaEventRecord(e2, s2);

    // join
    cudaStreamWaitEvent(0, e1, 0);
    cudaStreamWaitEvent(0, e2, 0);

    // s0: flash attention -> att split
    flash_hmma<<<dim3(T_/128, B_*H_), 256, FSM>>>(qh, ql, kh, kl, vh, vl, atth, attl);

    // s0: out = att·Wo^T + bo  [16384x512x512]
    hmma_ps<0><<<dim3(4, 128, 1), 256, GSM>>>(
        atth, attl, woh, wol, bo, out, nullptr, nullptr, T_*B_, E_, E_, E_, 1.f);

    (void)in_sizes; (void)n_in; (void)out_size;
}